// round 11
// baseline (speedup 1.0000x reference)
#include <cuda_runtime.h>
#include <cuda_bf16.h>
#include <math.h>
#include <stdint.h>

#define HID 1024
#define NHEADS 16
#define HEADDIM 64
#define BATCH 2
#define SEQ 2048
#define MROWS (BATCH * SEQ)   // 4096

#define QSCALE (0.125f * 1.4426950408889634f)   // 1/sqrt(64) * log2(e), folded into q

typedef __nv_bfloat16 bf16;

// ---------------- scratch ----------------
// bf16 path (v-proj + attention)
__device__ bf16 g_kvin_h[(size_t)MROWS * HID];
__device__ bf16 g_kvin_l[(size_t)MROWS * HID];
__device__ bf16 g_qh    [(size_t)MROWS * HID];
__device__ bf16 g_ql    [(size_t)MROWS * HID];
__device__ bf16 g_kvh   [(size_t)MROWS * 2 * HID];
__device__ bf16 g_kvl   [(size_t)MROWS * 2 * HID];
__device__ bf16 g_wvT_h [(size_t)HID * HID];
__device__ bf16 g_wvT_l [(size_t)HID * HID];
__device__ float g_yf   [(size_t)MROWS * HID];
// int8 path
__device__ int8_t g_qa_hi[(size_t)MROWS * HID];
__device__ int8_t g_qa_lo[(size_t)MROWS * HID];
__device__ int8_t g_ka_hi[(size_t)MROWS * HID];
__device__ int8_t g_ka_lo[(size_t)MROWS * HID];
__device__ int8_t g_ya_hi[(size_t)MROWS * HID];
__device__ int8_t g_ya_lo[(size_t)MROWS * HID];
__device__ int8_t g_wq8_h[(size_t)HID * HID];
__device__ int8_t g_wq8_l[(size_t)HID * HID];
__device__ int8_t g_wk8_h[(size_t)HID * HID];
__device__ int8_t g_wk8_l[(size_t)HID * HID];
__device__ int8_t g_wc8_h[(size_t)HID * HID];
__device__ int8_t g_wc8_l[(size_t)HID * HID];
__device__ float g_qa_s[MROWS];
__device__ float g_ka_s[MROWS];
__device__ float g_ya_s[MROWS];
__device__ float g_wq_s[HID];
__device__ float g_wk_s[HID];
__device__ float g_wc_s[HID];

// ---------------- PTX helpers ----------------
__device__ __forceinline__ uint32_t smem_u32(const void* p) {
    uint32_t a;
    asm("{ .reg .u64 t; cvta.to.shared.u64 t, %1; cvt.u32.u64 %0, t; }" : "=r"(a) : "l"(p));
    return a;
}
__device__ __forceinline__ void cp16(uint32_t s, const void* g) {
    asm volatile("cp.async.cg.shared.global [%0], [%1], 16;" :: "r"(s), "l"(g));
}
#define CP_COMMIT() asm volatile("cp.async.commit_group;" ::: "memory")
#define CP_WAIT1()  asm volatile("cp.async.wait_group 1;" ::: "memory")

__device__ __forceinline__ void ldsm4(uint32_t* r, uint32_t a) {
    asm volatile("ldmatrix.sync.aligned.m8n8.x4.shared.b16 {%0,%1,%2,%3}, [%4];"
                 : "=r"(r[0]), "=r"(r[1]), "=r"(r[2]), "=r"(r[3]) : "r"(a));
}
__device__ __forceinline__ void ldsm4t(uint32_t* r, uint32_t a) {
    asm volatile("ldmatrix.sync.aligned.m8n8.x4.trans.shared.b16 {%0,%1,%2,%3}, [%4];"
                 : "=r"(r[0]), "=r"(r[1]), "=r"(r[2]), "=r"(r[3]) : "r"(a));
}
__device__ __forceinline__ void mma16816(float* d, const uint32_t* a, const uint32_t* b) {
    asm volatile(
        "mma.sync.aligned.m16n8k16.row.col.f32.bf16.bf16.f32 "
        "{%0,%1,%2,%3}, {%4,%5,%6,%7}, {%8,%9}, {%0,%1,%2,%3};"
        : "+f"(d[0]), "+f"(d[1]), "+f"(d[2]), "+f"(d[3])
        : "r"(a[0]), "r"(a[1]), "r"(a[2]), "r"(a[3]), "r"(b[0]), "r"(b[1]));
}
__device__ __forceinline__ void imma16832(int* d, const uint32_t* a, const uint32_t* b) {
    asm volatile(
        "mma.sync.aligned.m16n8k32.row.col.s32.s8.s8.s32 "
        "{%0,%1,%2,%3}, {%4,%5,%6,%7}, {%8,%9}, {%0,%1,%2,%3};"
        : "+r"(d[0]), "+r"(d[1]), "+r"(d[2]), "+r"(d[3])
        : "r"(a[0]), "r"(a[1]), "r"(a[2]), "r"(a[3]), "r"(b[0]), "r"(b[1]));
}

__device__ __forceinline__ uint32_t pack2(float a, float b) {
    __nv_bfloat162 t = __floats2bfloat162_rn(a, b);
    return *(uint32_t*)&t;
}
__device__ __forceinline__ uint32_t pack2_res(float a, float b, uint32_t hpk) {
    __nv_bfloat162 hh = *(__nv_bfloat162*)&hpk;
    return pack2(a - __bfloat162float(hh.x), b - __bfloat162float(hh.y));
}
__device__ __forceinline__ void split_store(bf16* H, bf16* L, size_t idx, float a, float b) {
    uint32_t h = pack2(a, b);
    uint32_t l = pack2_res(a, b, h);
    *(uint32_t*)(H + idx) = h;
    *(uint32_t*)(L + idx) = l;
}

// ================= int8 3-term IMMA GEMM core =================
// C[M,N] = (sa_m * A15)[M,K] . (sb_n * B15)^T, A15 = Ah*128+Al int8 pairs,
// B stored [N,K] row-major int8 pairs. CTA 128x128, BK=64 (int8 bytes), 8 warps.
#define GP8    80
#define GMAT8  (128 * GP8)    // 10240
#define GSTG8  (4 * GMAT8)    // 40960
#define GSMEM8 (2 * GSTG8)    // 81920

template<int OUTMODE>   // 0: fp32 direct, 1: split-bf16 (scaled)
__device__ __forceinline__ void i8gemm_core(
    uint32_t sb,
    const int8_t* __restrict__ Ah, const int8_t* __restrict__ Al,
    const int8_t* __restrict__ Bh, const int8_t* __restrict__ Bl,
    const float* __restrict__ sa, const float* __restrict__ sbn,
    float* __restrict__ Cf, bf16* __restrict__ Ch, bf16* __restrict__ Cl,
    int Cstride, int K, int m0, int n0, float outscale) {
    const int tid = threadIdx.x, lane = tid & 31, wid = tid >> 5;
    const int wm = (wid >> 1) << 5, wn = (wid & 1) << 6;

    // int8 ldmatrix lane addressing (b16-element view of 4-byte k-groups)
    const int arow = (lane & 7) + ((lane >> 3) & 1) * 8;   // A: row, row+8, then k+16
    const int akb  = ((lane >> 4) & 1) * 16;
    const int brow = (lane & 7) + ((lane >> 4) & 1) * 8;   // B: k+16 first, then n+8
    const int bkb  = ((lane >> 3) & 1) * 16;

    int acc14[2][8][4], acc7[2][8][4];
    #pragma unroll
    for (int i = 0; i < 2; i++)
        #pragma unroll
        for (int j = 0; j < 8; j++)
            #pragma unroll
            for (int r = 0; r < 4; r++) { acc14[i][j][r] = 0; acc7[i][j][r] = 0; }

    const int NCH = K >> 6;   // BK = 64 int8

    {   // preload chunk 0
        uint32_t d = sb;
        #pragma unroll
        for (int i = 0; i < 2; i++) {
            int idx = tid + (i << 8);
            int row = idx >> 2, c = idx & 3;
            uint32_t off = row * GP8 + c * 16;
            cp16(d + off,             Ah + (size_t)(m0 + row) * K + c * 16);
            cp16(d + GMAT8 + off,     Al + (size_t)(m0 + row) * K + c * 16);
            cp16(d + 2 * GMAT8 + off, Bh + (size_t)(n0 + row) * K + c * 16);
            cp16(d + 3 * GMAT8 + off, Bl + (size_t)(n0 + row) * K + c * 16);
        }
    }
    CP_COMMIT();

    for (int ch = 0; ch < NCH; ch++) {
        if (ch + 1 < NCH) {
            uint32_t d = sb + ((ch + 1) & 1) * GSTG8;
            int k0 = (ch + 1) << 6;
            #pragma unroll
            for (int i = 0; i < 2; i++) {
                int idx = tid + (i << 8);
                int row = idx >> 2, c = idx & 3;
                uint32_t off = row * GP8 + c * 16;
                cp16(d + off,             Ah + (size_t)(m0 + row) * K + k0 + c * 16);
                cp16(d + GMAT8 + off,     Al + (size_t)(m0 + row) * K + k0 + c * 16);
                cp16(d + 2 * GMAT8 + off, Bh + (size_t)(n0 + row) * K + k0 + c * 16);
                cp16(d + 3 * GMAT8 + off, Bl + (size_t)(n0 + row) * K + k0 + c * 16);
            }
        }
        CP_COMMIT();
        CP_WAIT1();
        __syncthreads();

        const uint32_t base = sb + (ch & 1) * GSTG8;
        #pragma unroll
        for (int kk = 0; kk < 2; kk++) {
            const int kb = kk * 32;
            uint32_t ah8[2][4], al8[2][4];
            #pragma unroll
            for (int sm = 0; sm < 2; sm++) {
                uint32_t aoff = (wm + sm * 16 + arow) * GP8 + kb + akb;
                ldsm4(ah8[sm], base + aoff);
                ldsm4(al8[sm], base + GMAT8 + aoff);
            }
            uint32_t bh8[4][4], bl8[4][4];
            #pragma unroll
            for (int g = 0; g < 4; g++) {
                uint32_t boff = (wn + g * 16 + brow) * GP8 + kb + bkb;
                ldsm4(bh8[g], base + 2 * GMAT8 + boff);
                ldsm4(bl8[g], base + 3 * GMAT8 + boff);
            }
            #pragma unroll
            for (int sm = 0; sm < 2; sm++)
                #pragma unroll
                for (int nt = 0; nt < 8; nt++) {
                    const uint32_t* BH = &bh8[nt >> 1][(nt & 1) << 1];
                    const uint32_t* BL = &bl8[nt >> 1][(nt & 1) << 1];
                    imma16832(acc14[sm][nt], ah8[sm], BH);   // hi*hi  (x 2^14)
                    imma16832(acc7[sm][nt],  ah8[sm], BL);   // hi*lo  (x 2^7)
                    imma16832(acc7[sm][nt],  al8[sm], BH);   // lo*hi  (x 2^7)
                }
        }
        __syncthreads();
    }

    // epilogue: dequant + store
    const int r0 = wm + (lane >> 2);
    const int c0 = wn + ((lane & 3) << 1);
    #pragma unroll
    for (int sm = 0; sm < 2; sm++) {
        const int row = m0 + r0 + sm * 16;
        const float sa0 = sa[row] * outscale;
        const float sa1 = sa[row + 8] * outscale;
        #pragma unroll
        for (int nt = 0; nt < 8; nt++) {
            const int coln = n0 + c0 + nt * 8;
            const float sb0 = sbn[coln], sb1 = sbn[coln + 1];
            float v00 = fmaf((float)acc14[sm][nt][0], 16384.f, (float)acc7[sm][nt][0] * 128.f) * (sa0 * sb0);
            float v01 = fmaf((float)acc14[sm][nt][1], 16384.f, (float)acc7[sm][nt][1] * 128.f) * (sa0 * sb1);
            float v10 = fmaf((float)acc14[sm][nt][2], 16384.f, (float)acc7[sm][nt][2] * 128.f) * (sa1 * sb0);
            float v11 = fmaf((float)acc14[sm][nt][3], 16384.f, (float)acc7[sm][nt][3] * 128.f) * (sa1 * sb1);
            if (OUTMODE == 0) {
                *(float2*)(Cf + (size_t)row * Cstride + coln)       = make_float2(v00, v01);
                *(float2*)(Cf + (size_t)(row + 8) * Cstride + coln) = make_float2(v10, v11);
            } else {
                split_store(Ch, Cl, (size_t)row * Cstride + coln, v00, v01);
                split_store(Ch, Cl, (size_t)(row + 8) * Cstride + coln, v10, v11);
            }
        }
    }
}

// merged q-proj + k-proj int8 launch
__global__ __launch_bounds__(256, 1)
void qkproj_i8(const int8_t* __restrict__ qah, const int8_t* __restrict__ qal,
               const int8_t* __restrict__ kah, const int8_t* __restrict__ kal,
               const int8_t* __restrict__ wqh, const int8_t* __restrict__ wql,
               const int8_t* __restrict__ wkh, const int8_t* __restrict__ wkl,
               const float* __restrict__ qas, const float* __restrict__ kas,
               const float* __restrict__ wqs, const float* __restrict__ wks,
               bf16* __restrict__ qh, bf16* __restrict__ ql,
               bf16* __restrict__ kvh, bf16* __restrict__ kvl) {
    extern __shared__ __align__(128) char smem[];
    const uint32_t sb = smem_u32(smem);
    const int bx = blockIdx.x, m0 = blockIdx.y << 7;
    if (bx < HID / 128) {
        i8gemm_core<1>(sb, qah, qal, wqh, wql, qas, wqs, nullptr, qh, ql,
                       HID, HID, m0, bx << 7, QSCALE);
    } else {
        i8gemm_core<1>(sb, kah, kal, wkh, wkl, kas, wks, nullptr, kvh, kvl,
                       2 * HID, HID, m0, (bx - HID / 128) << 7, 1.0f);
    }
}

__global__ __launch_bounds__(256, 1)
void outproj_i8(const int8_t* __restrict__ yah, const int8_t* __restrict__ yal,
                const int8_t* __restrict__ wch, const int8_t* __restrict__ wcl,
                const float* __restrict__ yas, const float* __restrict__ wcs,
                float* __restrict__ out) {
    extern __shared__ __align__(128) char smem[];
    const uint32_t sb = smem_u32(smem);
    i8gemm_core<0>(sb, yah, yal, wch, wcl, yas, wcs, out, nullptr, nullptr,
                   HID, HID, blockIdx.y << 7, blockIdx.x << 7, 1.0f);
}

// ================= bf16 split GEMM core (v-proj) =================
#define GP    80
#define GMAT  10240
#define GSTG  40960
#define GSMEM (2 * GSTG)

__global__ __launch_bounds__(256, 1)
void vproj_gemm(const bf16* __restrict__ Ah, const bf16* __restrict__ Al,
                const bf16* __restrict__ Bh, const bf16* __restrict__ Bl,
                bf16* __restrict__ Ch, bf16* __restrict__ Cl) {
    extern __shared__ __align__(128) char smem[];
    const uint32_t sb = smem_u32(smem);
    const int tid = threadIdx.x, lane = tid & 31, wid = tid >> 5;
    const int m0 = blockIdx.y << 7, n0 = blockIdx.x << 7;
    const int wm = (wid >> 1) << 5, wn = (wid & 1) << 6;
    const int N = 2 * HID, K = HID;   // C stride 2048 (writes v-half via +HID base)

    const int arow  = (lane & 7) + ((lane >> 3) & 1) * 8;
    const int akoff = ((lane >> 4) << 3);
    const int brow  = (lane & 7) + ((lane >> 4) << 3);
    const int bkoff = ((lane >> 3) & 1) * 8;

    float acc[2][8][4];
    #pragma unroll
    for (int i = 0; i < 2; i++)
        #pragma unroll
        for (int j = 0; j < 8; j++)
            #pragma unroll
            for (int r = 0; r < 4; r++) acc[i][j][r] = 0.f;

    const int NCH = K >> 5;
    {
        uint32_t d = sb;
        #pragma unroll
        for (int i = 0; i < 2; i++) {
            int idx = tid + (i << 8);
            int row = idx >> 2, c = idx & 3;
            uint32_t off = row * GP + c * 16;
            cp16(d + off,            Ah + (size_t)(m0 + row) * K + c * 8);
            cp16(d + GMAT + off,     Al + (size_t)(m0 + row) * K + c * 8);
            cp16(d + 2 * GMAT + off, Bh + (size_t)(n0 + row) * K + c * 8);
            cp16(d + 3 * GMAT + off, Bl + (size_t)(n0 + row) * K + c * 8);
        }
    }
    CP_COMMIT();

    for (int ch = 0; ch < NCH; ch++) {
        if (ch + 1 < NCH) {
            uint32_t d = sb + ((ch + 1) & 1) * GSTG;
            int k0 = (ch + 1) << 5;
            #pragma unroll
            for (int i = 0; i < 2; i++) {
                int idx = tid + (i << 8);
                int row = idx >> 2, c = idx & 3;
                uint32_t off = row * GP + c * 16;
                cp16(d + off,            Ah + (size_t)(m0 + row) * K + k0 + c * 8);
                cp16(d + GMAT + off,     Al + (size_t)(m0 + row) * K + k0 + c * 8);
                cp16(d + 2 * GMAT + off, Bh + (size_t)(n0 + row) * K + k0 + c * 8);
                cp16(d + 3 * GMAT + off, Bl + (size_t)(n0 + row) * K + k0 + c * 8);
            }
        }
        CP_COMMIT();
        CP_WAIT1();
        __syncthreads();

        const uint32_t base = sb + (ch & 1) * GSTG;
        #pragma unroll
        for (int kk = 0; kk < 2; kk++) {
            uint32_t ah[2][4], al[2][4];
            #pragma unroll
            for (int sm = 0; sm < 2; sm++) {
                uint32_t aoff = (wm + sm * 16 + arow) * GP + (kk * 16 + akoff) * 2;
                ldsm4(ah[sm], base + aoff);
                ldsm4(al[sm], base + GMAT + aoff);
            }
            uint32_t bh4[4][4], bl4[4][4];
            #pragma unroll
            for (int q = 0; q < 4; q++) {
                uint32_t boff = (wn + q * 16 + brow) * GP + (kk * 16 + bkoff) * 2;
                ldsm4(bh4[q], base + 2 * GMAT + boff);
                ldsm4(bl4[q], base + 3 * GMAT + boff);
            }
            #pragma unroll
            for (int sm = 0; sm < 2; sm++)
                #pragma unroll
                for (int nt = 0; nt < 8; nt++) {
                    const uint32_t* BH = &bh4[nt >> 1][(nt & 1) << 1];
                    const uint32_t* BL = &bl4[nt >> 1][(nt & 1) << 1];
                    mma16816(acc[sm][nt], ah[sm], BH);
                    mma16816(acc[sm][nt], ah[sm], BL);
                    mma16816(acc[sm][nt], al[sm], BH);
                }
        }
        __syncthreads();
    }

    const int r0 = wm + (lane >> 2);
    const int c0 = wn + ((lane & 3) << 1);
    #pragma unroll
    for (int sm = 0; sm < 2; sm++)
        #pragma unroll
        for (int nt = 0; nt < 8; nt++) {
            int row = m0 + r0 + sm * 16;
            int col = n0 + c0 + nt * 8;
            split_store(Ch, Cl, (size_t)row * N + col, acc[sm][nt][0], acc[sm][nt][1]);
            split_store(Ch, Cl, (size_t)(row + 8) * N + col, acc[sm][nt][2], acc[sm][nt][3]);
        }
}

// ================= flash attention on mma.sync (unchanged math; fp32 y out) ====
#define AP     144
#define AQMAT  (128 * AP)
#define AM2    (128 * AP)
#define ASTG   (4 * AM2)
#define ASMEM  (2 * AQMAT + 2 * ASTG)

__global__ __launch_bounds__(256, 1)
void attn_mma(const bf16* __restrict__ qh, const bf16* __restrict__ ql,
              const bf16* __restrict__ kvh, const bf16* __restrict__ kvl,
              float* __restrict__ yf) {
    extern __shared__ __align__(128) char smem[];
    const uint32_t sb = smem_u32(smem);
    const int tid = threadIdx.x, lane = tid & 31, wid = tid >> 5;
    const int bh = blockIdx.y;
    const int b = bh >> 4, h = bh & 15;
    const int q0 = blockIdx.x << 7;

    const int arow  = (lane & 7) + ((lane >> 3) & 1) * 8;
    const int akoff = ((lane >> 4) << 3);
    const int brow  = (lane & 7) + ((lane >> 4) << 3);
    const int bkoff = ((lane >> 3) & 1) * 8;

    const uint32_t sQh = sb, sQl = sb + AQMAT;
    const uint32_t sKV = sb + 2 * AQMAT;

    #pragma unroll
    for (int i = 0; i < 4; i++) {
        int idx = tid + (i << 8);
        int row = idx >> 3, c = idx & 7;
        uint32_t off = row * AP + c * 16;
        const size_t g = (size_t)(b * SEQ + q0 + row) * HID + h * HEADDIM + c * 8;
        cp16(sQh + off, qh + g);
        cp16(sQl + off, ql + g);
    }
    CP_COMMIT();

    const size_t kvrow0 = (size_t)(b * SEQ);
    #pragma unroll
    for (int i = 0; i < 4; i++) {
        int idx = tid + (i << 8);
        int row = idx >> 3, c = idx & 7;
        uint32_t off = row * AP + c * 16;
        size_t gk = (kvrow0 + row) * (2 * HID) + h * HEADDIM + c * 8;
        size_t gv = gk + HID;
        cp16(sKV + off,           kvh + gk);
        cp16(sKV + AM2 + off,     kvl + gk);
        cp16(sKV + 2 * AM2 + off, kvh + gv);
        cp16(sKV + 3 * AM2 + off, kvl + gv);
    }
    CP_COMMIT();
    CP_WAIT1();
    __syncthreads();

    uint32_t qfh[4][4], qfl[4][4];
    #pragma unroll
    for (int kk = 0; kk < 4; kk++) {
        uint32_t off = (wid * 16 + arow) * AP + (kk * 16 + akoff) * 2;
        ldsm4(qfh[kk], sQh + off);
        ldsm4(qfl[kk], sQl + off);
    }

    float o[8][4];
    #pragma unroll
    for (int i = 0; i < 8; i++)
        #pragma unroll
        for (int r = 0; r < 4; r++) o[i][r] = 0.f;
    float m0_ = -INFINITY, m1_ = -INFINITY, l0_ = 0.f, l1_ = 0.f;

    const int NIT = SEQ / 128;
    for (int ch = 0; ch < NIT; ch++) {
        if (ch + 1 < NIT) {
            uint32_t d = sKV + ((ch + 1) & 1) * ASTG;
            int t0 = (ch + 1) << 7;
            #pragma unroll
            for (int i = 0; i < 4; i++) {
                int idx = tid + (i << 8);
                int row = idx >> 3, c = idx & 7;
                uint32_t off = row * AP + c * 16;
                size_t gk = (kvrow0 + t0 + row) * (2 * HID) + h * HEADDIM + c * 8;
                size_t gv = gk + HID;
                cp16(d + off,           kvh + gk);
                cp16(d + AM2 + off,     kvl + gk);
                cp16(d + 2 * AM2 + off, kvh + gv);
                cp16(d + 3 * AM2 + off, kvl + gv);
            }
        }
        CP_COMMIT();
        CP_WAIT1();
        __syncthreads();

        const uint32_t sK = sKV + (ch & 1) * ASTG;
        const uint32_t sV = sK + 2 * AM2;

        float sA[8][4], sB[8][4];
        #pragma unroll
        for (int i = 0; i < 8; i++)
            #pragma unroll
            for (int r = 0; r < 4; r++) { sA[i][r] = 0.f; sB[i][r] = 0.f; }

        #pragma unroll
        for (int kk = 0; kk < 4; kk++) {
            uint32_t kb[4][4], kl4[4][4];
            #pragma unroll
            for (int q = 0; q < 4; q++) {
                uint32_t off = (q * 16 + brow) * AP + (kk * 16 + bkoff) * 2;
                ldsm4(kb[q],  sK + off);
                ldsm4(kl4[q], sK + AM2 + off);
            }
            #pragma unroll
            for (int nt = 0; nt < 8; nt++) {
                const uint32_t* BH = &kb[nt >> 1][(nt & 1) << 1];
                const uint32_t* BL = &kl4[nt >> 1][(nt & 1) << 1];
                mma16816(sA[nt], qfh[kk], BH);
                mma16816(sA[nt], qfh[kk], BL);
                mma16816(sA[nt], qfl[kk], BH);
            }
        }
        #pragma unroll
        for (int kk = 0; kk < 4; kk++) {
            uint32_t kb[4][4], kl4[4][4];
            #pragma unroll
            for (int q = 0; q < 4; q++) {
                uint32_t off = ((64 + q * 16) + brow) * AP + (kk * 16 + bkoff) * 2;
                ldsm4(kb[q],  sK + off);
                ldsm4(kl4[q], sK + AM2 + off);
            }
            #pragma unroll
            for (int nt = 0; nt < 8; nt++) {
                const uint32_t* BH = &kb[nt >> 1][(nt & 1) << 1];
                const uint32_t* BL = &kl4[nt >> 1][(nt & 1) << 1];
                mma16816(sB[nt], qfh[kk], BH);
                mma16816(sB[nt], qfh[kk], BL);
                mma16816(sB[nt], qfl[kk], BH);
            }
        }

        float mx0 = -INFINITY, mx1 = -INFINITY;
        #pragma unroll
        for (int nt = 0; nt < 8; nt++) {
            mx0 = fmaxf(mx0, fmaxf(fmaxf(sA[nt][0], sA[nt][1]), fmaxf(sB[nt][0], sB[nt][1])));
            mx1 = fmaxf(mx1, fmaxf(fmaxf(sA[nt][2], sA[nt][3]), fmaxf(sB[nt][2], sB[nt][3])));
        }
        mx0 = fmaxf(mx0, __shfl_xor_sync(0xffffffffu, mx0, 1));
        mx0 = fmaxf(mx0, __shfl_xor_sync(0xffffffffu, mx0, 2));
        mx1 = fmaxf(mx1, __shfl_xor_sync(0xffffffffu, mx1, 1));
        mx1 = fmaxf(mx1, __shfl_xor_sync(0xffffffffu, mx1, 2));
        float mn0 = fmaxf(m0_, mx0), mn1 = fmaxf(m1_, mx1);
        float corr0 = exp2f(m0_ - mn0), corr1 = exp2f(m1_ - mn1);
        m0_ = mn0; m1_ = mn1;

        float rs0 = 0.f, rs1 = 0.f;
        uint32_t phA[4][4], plA[4][4];
        #pragma unroll
        for (int nt = 0; nt < 8; nt++) {
            sA[nt][0] = exp2f(sA[nt][0] - mn0); rs0 += sA[nt][0];
            sA[nt][1] = exp2f(sA[nt][1] - mn0); rs0 += sA[nt][1];
            sA[nt][2] = exp2f(sA[nt][2] - mn1); rs1 += sA[nt][2];
            sA[nt][3] = exp2f(sA[nt][3] - mn1); rs1 += sA[nt][3];
        }
        #pragma unroll
        for (int j = 0; j < 4; j++) {
            phA[j][0] = pack2(sA[2*j][0], sA[2*j][1]);
            phA[j][1] = pack2(sA[2*j][2], sA[2*j][3]);
            phA[j][2] = pack2(sA[2*j+1][0], sA[2*j+1][1]);
            phA[j][3] = pack2(sA[2*j+1][2], sA[2*j+1][3]);
            plA[j][0] = pack2_res(sA[2*j][0], sA[2*j][1], phA[j][0]);
            plA[j][1] = pack2_res(sA[2*j][2], sA[2*j][3], phA[j][1]);
            plA[j][2] = pack2_res(sA[2*j+1][0], sA[2*j+1][1], phA[j][2]);
            plA[j][3] = pack2_res(sA[2*j+1][2], sA[2*j+1][3], phA[j][3]);
        }

        #pragma unroll
        for (int dt = 0; dt < 8; dt++) {
            o[dt][0] *= corr0; o[dt][1] *= corr0;
            o[dt][2] *= corr1; o[dt][3] *= corr1;
        }

        #pragma unroll
        for (int j = 0; j < 4; j++) {
            uint32_t vb[4][4], vl4[4][4];
            #pragma unroll
            for (int dq = 0; dq < 4; dq++) {
                uint32_t off = (j * 16 + arow) * AP + (dq * 16 + akoff) * 2;
                ldsm4t(vb[dq],  sV + off);
                ldsm4t(vl4[dq], sV + AM2 + off);
            }
            #pragma unroll
            for (int dt = 0; dt < 8; dt++) {
                const uint32_t* VH = &vb[dt >> 1][(dt & 1) << 1];
                const uint32_t* VL = &vl4[dt >> 1][(dt & 1) << 1];
                mma16816(o[dt], phA[j], VH);
                mma16816(o[dt], phA[j], VL);
                mma16816(o[dt], plA[j], VH);
            }
        }

        uint32_t phB[4][4], plB[4][4];
        #pragma unroll
        for (int nt = 0; nt < 8; nt++) {
            sB[nt][0] = exp2f(sB[nt][0] - mn0); rs0 += sB[nt][0];
            sB[nt][1] = exp2f(sB[nt][1] - mn0); rs0 += sB[nt][1];
            sB[nt][2] = exp2f(sB[nt][2] - mn1); rs1 += sB[nt][2];
            sB[nt][3] = exp2f(sB[nt][3] - mn1); rs1 += sB[nt][3];
        }
        #pragma unroll
        for (int j = 0; j < 4; j++) {
            phB[j][0] = pack2(sB[2*j][0], sB[2*j][1]);
            phB[j][1] = pack2(sB[2*j][2], sB[2*j][3]);
            phB[j][2] = pack2(sB[2*j+1][0], sB[2*j+1][1]);
            phB[j][3] = pack2(sB[2*j+1][2], sB[2*j+1][3]);
            plB[j][0] = pack2_res(sB[2*j][0], sB[2*j][1], phB[j][0]);
            plB[j][1] = pack2_res(sB[2*j][2], sB[2*j][3], phB[j][1]);
            plB[j][2] = pack2_res(sB[2*j+1][0], sB[2*j+1][1], phB[j][2]);
            plB[j][3] = pack2_res(sB[2*j+1][2], sB[2*j+1][3], phB[j][3]);
        }

        rs0 += __shfl_xor_sync(0xffffffffu, rs0, 1);
        rs0 += __shfl_xor_sync(0xffffffffu, rs0, 2);
        rs1 += __shfl_xor_sync(0xffffffffu, rs1, 1);
        rs1 += __shfl_xor_sync(0xffffffffu, rs1, 2);
        l0_ = l0_ * corr0 + rs0;
        l1_ = l1_ * corr1 + rs1;

        #pragma unroll
        for (int j = 0; j < 4; j++) {
            uint32_t vb[4][4], vl4[4][4];
            #pragma unroll
            for (int dq = 0; dq < 4; dq++) {
                uint32_t off = ((64 + j * 16) + arow) * AP + (dq * 16 + akoff) * 2;
                ldsm4t(vb[dq],  sV + off);
                ldsm4t(vl4[dq], sV + AM2 + off);
            }
            #pragma unroll
            for (int dt = 0; dt < 8; dt++) {
                const uint32_t* VH = &vb[dt >> 1][(dt & 1) << 1];
                const uint32_t* VL = &vl4[dt >> 1][(dt & 1) << 1];
                mma16816(o[dt], phB[j], VH);
                mma16816(o[dt], phB[j], VL);
                mma16816(o[dt], plB[j], VH);
            }
        }
        __syncthreads();
    }

    const float inv0 = 1.f / l0_, inv1 = 1.f / l1_;
    const int gr = b * SEQ + q0 + wid * 16 + (lane >> 2);
    const int col = h * HEADDIM + ((lane & 3) << 1);
    #pragma unroll
    for (int dt = 0; dt < 8; dt++) {
        *(float2*)(yf + (size_t)gr * HID + col + dt * 8) =
            make_float2(o[dt][0] * inv0, o[dt][1] * inv0);
        *(float2*)(yf + (size_t)(gr + 8) * HID + col + dt * 8) =
            make_float2(o[dt][2] * inv1, o[dt][3] * inv1);
    }
}

// ---------------- quantizers / converters ----------------
// per-row int15 quantize -> int8 hi/lo + scale. K must be 1024, block 256.
__global__ void act_quant8(const float* __restrict__ A, int8_t* __restrict__ H,
                           int8_t* __restrict__ L, float* __restrict__ S) {
    __shared__ float red[8];
    const int row = blockIdx.x, t = threadIdx.x;
    float v[4];
    float m = 0.f;
    #pragma unroll
    for (int j = 0; j < 4; j++) {
        v[j] = A[(size_t)row * HID + t + j * 256];
        m = fmaxf(m, fabsf(v[j]));
    }
    #pragma unroll
    for (int off = 16; off > 0; off >>= 1)
        m = fmaxf(m, __shfl_xor_sync(0xffffffffu, m, off));
    if ((t & 31) == 0) red[t >> 5] = m;
    __syncthreads();
    float mm = fmaxf(fmaxf(fmaxf(red[0], red[1]), fmaxf(red[2], red[3])),
                     fmaxf(fmaxf(red[4], red[5]), fmaxf(red[6], red[7])));
    const float inv = mm > 0.f ? 16256.f / mm : 0.f;
    if (t == 0) S[row] = mm * (1.f / 16256.f);
    #pragma unroll
    for (int j = 0; j < 4; j++) {
        int vi = __float2int_rn(v[j] * inv);
        int hi = (vi + 64) >> 7;
        int lo = vi - (hi << 7);
        H[(size_t)row * HID + t + j * 256] = (int8_t)hi;
        L[(size_t)row * HID + t + j * 256] = (int8_t)lo;
    }
}

// weight quantize + transpose: W[K=1024, *] column (colbase implicit via ptr) -> row n of [N,K]
__global__ void wquant8(const float* __restrict__ W, int wstride,
                        int8_t* __restrict__ H, int8_t* __restrict__ L,
                        float* __restrict__ S) {
    __shared__ float red[8];
    const int n = blockIdx.x, t = threadIdx.x;
    float v[4];
    float m = 0.f;
    #pragma unroll
    for (int j = 0; j < 4; j++) {
        v[j] = W[(size_t)(t + j * 256) * wstride + n];
        m = fmaxf(m, fabsf(v[j]));
    }
    #pragma unroll
    for (int off = 16; off > 0; off >>= 1)
        m = fmaxf(m, __shfl_xor_sync(0xffffffffu, m, off));
    if ((t & 31) == 0) red[t >> 5] = m;
    __syncthreads();
    float mm = fmaxf(fmaxf(fmaxf(red[0], red[1]), fmaxf(red[2], red[3])),
                     fmaxf(fmaxf(red[4], red[5]), fmaxf(red[6], red[7])));
    const float inv = mm > 0.f ? 16256.f / mm : 0.f;
    if (t == 0) S[n] = mm * (1.f / 16256.f);
    #pragma unroll
    for (int j = 0; j < 4; j++) {
        int vi = __float2int_rn(v[j] * inv);
        int hi = (vi + 64) >> 7;
        int lo = vi - (hi << 7);
        H[(size_t)n * HID + t + j * 256] = (int8_t)hi;
        L[(size_t)n * HID + t + j * 256] = (int8_t)lo;
    }
}

__global__ void convert_act(const float* __restrict__ in, bf16* __restrict__ h,
                            bf16* __restrict__ l, int n) {
    int i = (blockIdx.x * blockDim.x + threadIdx.x) << 2;
    if (i >= n) return;
    float4 v = *(const float4*)(in + i);
    uint32_t h0 = pack2(v.x, v.y), h1 = pack2(v.z, v.w);
    uint32_t l0 = pack2_res(v.x, v.y, h0), l1 = pack2_res(v.z, v.w, h1);
    *(uint32_t*)(h + i) = h0; *(uint32_t*)(h + i + 2) = h1;
    *(uint32_t*)(l + i) = l0; *(uint32_t*)(l + i + 2) = l1;
}

// W[K,N] fp32 -> Th/Tl[N',K] bf16 (transpose + split); pass pre-offset W pointer
__global__ void trconv(const float* __restrict__ W, bf16* __restrict__ Th,
                       bf16* __restrict__ Tl, int K, int N) {
    __shared__ float t[32][33];
    const int n0 = blockIdx.x << 5, k0 = blockIdx.y << 5;
    const int tx = threadIdx.x, ty = threadIdx.y;
    #pragma unroll
    for (int j = 0; j < 32; j += 8)
        t[ty + j][tx] = W[(size_t)(k0 + ty + j) * N + n0 + tx];
    __syncthreads();
    #pragma unroll
    for (int j = 0; j < 32; j += 8) {
        float v = t[tx][ty + j];
        bf16 hv = __float2bfloat16(v);
        bf16 lv = __float2bfloat16(v - __bfloat162float(hv));
        size_t off = (size_t)(n0 + ty + j) * K + k0 + tx;
        Th[off] = hv;
        Tl[off] = lv;
    }
}

// ---------------- launch ----------------
extern "C" void kernel_launch(void* const* d_in, const int* in_sizes, int n_in,
                              void* d_out, int out_size) {
    const float* query     = (const float*)d_in[0];
    const float* key_value = (const float*)d_in[1];
    const float* Wq        = (const float*)d_in[2];
    const float* Wkv       = (const float*)d_in[3];
    const float* Wc        = (const float*)d_in[4];
    float* out = (float*)d_out;

    bf16 *kvin_h, *kvin_l, *qqh, *qql, *kvh, *kvl, *wvh, *wvl;
    float *yf, *qas, *kas, *yas, *wqs, *wks, *wcs;
    int8_t *qah, *qal, *kah, *kal, *yah, *yal, *wq8h, *wq8l, *wk8h, *wk8l, *wc8h, *wc8l;
    cudaGetSymbolAddress((void**)&kvin_h, g_kvin_h);
    cudaGetSymbolAddress((void**)&kvin_l, g_kvin_l);
    cudaGetSymbolAddress((void**)&qqh,    g_qh);
    cudaGetSymbolAddress((void**)&qql,    g_ql);
    cudaGetSymbolAddress((void**)&kvh,    g_kvh);
    cudaGetSymbolAddress((void**)&kvl,    g_kvl);
    cudaGetSymbolAddress((void**)&wvh,    g_wvT_h);
    cudaGetSymbolAddress((void**)&wvl,    g_wvT_l);
    cudaGetSymbolAddress((void**)&yf,     g_yf);
    cudaGetSymbolAddress((void**)&qah,    g_qa_hi);
    cudaGetSymbolAddress((void**)&qal,    g_qa_lo);
    cudaGetSymbolAddress((void**)&kah,    g_ka_hi);
    cudaGetSymbolAddress((void**)&kal,    g_ka_lo);
    cudaGetSymbolAddress((void**)&yah,    g_ya_hi);
    cudaGetSymbolAddress((void**)&yal,    g_ya_lo);
    cudaGetSymbolAddress((void**)&wq8h,   g_wq8_h);
    cudaGetSymbolAddress((void**)&wq8l,   g_wq8_l);
    cudaGetSymbolAddress((void**)&wk8h,   g_wk8_h);
    cudaGetSymbolAddress((void**)&wk8l,   g_wk8_l);
    cudaGetSymbolAddress((void**)&wc8h,   g_wc8_h);
    cudaGetSymbolAddress((void**)&wc8l,   g_wc8_l);
    cudaGetSymbolAddress((void**)&qas,    g_qa_s);
    cudaGetSymbolAddress((void**)&kas,    g_ka_s);
    cudaGetSymbolAddress((void**)&yas,    g_ya_s);
    cudaGetSymbolAddress((void**)&wqs,    g_wq_s);
    cudaGetSymbolAddress((void**)&wks,    g_wk_s);
    cudaGetSymbolAddress((void**)&wcs,    g_wc_s);

    cudaFuncSetAttribute(qkproj_i8,  cudaFuncAttributeMaxDynamicSharedMemorySize, GSMEM8);
    cudaFuncSetAttribute(outproj_i8, cudaFuncAttributeMaxDynamicSharedMemorySize, GSMEM8);
    cudaFuncSetAttribute(vproj_gemm, cudaFuncAttributeMaxDynamicSharedMemorySize, GSMEM);
    cudaFuncSetAttribute(attn_mma,   cudaFuncAttributeMaxDynamicSharedMemorySize, ASMEM);

    // quantize activations (int8) + v-path bf16 convert
    act_quant8<<<MROWS, 256>>>(query, qah, qal, qas);
    act_quant8<<<MROWS, 256>>>(key_value, kah, kal, kas);
    convert_act<<<MROWS * HID / 4 / 256, 256>>>(key_value, kvin_h, kvin_l, MROWS * HID);

    // quantize / convert weights
    wquant8<<<HID, 256>>>(Wq,  HID,     wq8h, wq8l, wqs);
    wquant8<<<HID, 256>>>(Wkv, 2 * HID, wk8h, wk8l, wks);          // k-half: cols 0-1023
    trconv<<<dim3(HID / 32, HID / 32), dim3(32, 8)>>>(Wkv + HID, wvh, wvl, HID, 2 * HID);
    wquant8<<<HID, 256>>>(Wc,  HID,     wc8h, wc8l, wcs);

    // q-proj + k-proj (int8, merged launch)
    qkproj_i8<<<dim3(2 * HID / 128, MROWS / 128), 256, GSMEM8>>>(
        qah, qal, kah, kal, wq8h, wq8l, wk8h, wk8l,
        qas, kas, wqs, wks, qqh, qql, kvh, kvl);

    // v-proj (bf16 3-term) -> kv cols 1024-2047
    vproj_gemm<<<dim3(HID / 128, MROWS / 128), 256, GSMEM>>>(
        kvin_h, kvin_l, wvh, wvl, kvh + HID, kvl + HID);

    // attention -> fp32 y
    attn_mma<<<dim3(SEQ / 128, BATCH * NHEADS), 256, ASMEM>>>(qqh, qql, kvh, kvl, yf);

    // quantize y, out-proj (int8)
    act_quant8<<<MROWS, 256>>>(yf, yah, yal, yas);
    outproj_i8<<<dim3(HID / 128, MROWS / 128), 256, GSMEM8>>>(
        yah, yal, wc8h, wc8l, yas, wcs, out);
}

// round 14
// speedup vs baseline: 2.2136x; 2.2136x over previous
#include <cuda_runtime.h>
#include <cuda_fp16.h>
#include <math.h>
#include <stdint.h>

#define HID 1024
#define NHEADS 16
#define HEADDIM 64
#define BATCH 2
#define SEQ 2048
#define MROWS (BATCH * SEQ)   // 4096

#define QSCALE (0.125f * 1.4426950408889634f)   // 1/sqrt(64) * log2(e), folded into q

typedef __half fp16;

// ---------------- scratch ----------------
__device__ fp16 g_qin [(size_t)MROWS * HID];
__device__ fp16 g_kvin[(size_t)MROWS * HID];
__device__ fp16 g_q   [(size_t)MROWS * HID];
__device__ fp16 g_kv  [(size_t)MROWS * 2 * HID];
__device__ fp16 g_y   [(size_t)MROWS * HID];
__device__ fp16 g_wqT [(size_t)HID * HID];
__device__ fp16 g_wkvT[(size_t)2 * HID * HID];
__device__ fp16 g_wcT [(size_t)HID * HID];

// ---------------- PTX helpers ----------------
__device__ __forceinline__ uint32_t smem_u32(const void* p) {
    uint32_t a;
    asm("{ .reg .u64 t; cvta.to.shared.u64 t, %1; cvt.u32.u64 %0, t; }" : "=r"(a) : "l"(p));
    return a;
}
__device__ __forceinline__ void cp16(uint32_t s, const void* g) {
    asm volatile("cp.async.cg.shared.global [%0], [%1], 16;" :: "r"(s), "l"(g));
}
#define CP_COMMIT() asm volatile("cp.async.commit_group;" ::: "memory")
#define CP_WAIT1()  asm volatile("cp.async.wait_group 1;" ::: "memory")

__device__ __forceinline__ void ldsm4(uint32_t* r, uint32_t a) {
    asm volatile("ldmatrix.sync.aligned.m8n8.x4.shared.b16 {%0,%1,%2,%3}, [%4];"
                 : "=r"(r[0]), "=r"(r[1]), "=r"(r[2]), "=r"(r[3]) : "r"(a));
}
__device__ __forceinline__ void ldsm4t(uint32_t* r, uint32_t a) {
    asm volatile("ldmatrix.sync.aligned.m8n8.x4.trans.shared.b16 {%0,%1,%2,%3}, [%4];"
                 : "=r"(r[0]), "=r"(r[1]), "=r"(r[2]), "=r"(r[3]) : "r"(a));
}
__device__ __forceinline__ void mma16816(float* d, const uint32_t* a, const uint32_t* b) {
    asm volatile(
        "mma.sync.aligned.m16n8k16.row.col.f32.f16.f16.f32 "
        "{%0,%1,%2,%3}, {%4,%5,%6,%7}, {%8,%9}, {%0,%1,%2,%3};"
        : "+f"(d[0]), "+f"(d[1]), "+f"(d[2]), "+f"(d[3])
        : "r"(a[0]), "r"(a[1]), "r"(a[2]), "r"(a[3]), "r"(b[0]), "r"(b[1]));
}

__device__ __forceinline__ uint32_t pack2(float a, float b) {
    __half2 t = __floats2half2_rn(a, b);
    return *(uint32_t*)&t;
}

// ================= fp16 mma.sync GEMM core =================
// C[M,N] = A[M,K] . B^T, B stored [N,K] row-major (pre-transposed).
// CTA tile 128x128, BK=32, 8 warps (4m x 2n), warp tile 32x64.
#define GP    80      // smem pitch bytes per 32-fp16 row
#define GMAT  10240   // 128 rows * 80B
#define GSTG  (2 * GMAT)      // A + B per stage = 20480
#define GSMEM (2 * GSTG)      // 40960

template<int MODE>   // 0: fp32 out, 1: fp16 out (scaled)
__device__ __forceinline__ void gemm_core(
    uint32_t sb,
    const fp16* __restrict__ A, const fp16* __restrict__ B,
    float* __restrict__ Cf, fp16* __restrict__ Ch,
    int N, int K, int m0, int n0, float scale) {
    const int tid = threadIdx.x, lane = tid & 31, wid = tid >> 5;
    const int wm = (wid >> 1) << 5, wn = (wid & 1) << 6;

    const int arow  = (lane & 7) + ((lane >> 3) & 1) * 8;
    const int akoff = ((lane >> 4) << 3);
    const int brow  = (lane & 7) + ((lane >> 4) << 3);
    const int bkoff = ((lane >> 3) & 1) * 8;

    float acc[2][8][4];
    #pragma unroll
    for (int i = 0; i < 2; i++)
        #pragma unroll
        for (int j = 0; j < 8; j++)
            #pragma unroll
            for (int r = 0; r < 4; r++) acc[i][j][r] = 0.f;

    const int NCH = K >> 5;

    {   // preload chunk 0
        #pragma unroll
        for (int i = 0; i < 2; i++) {
            int idx = tid + (i << 8);
            int row = idx >> 2, c = idx & 3;
            uint32_t off = row * GP + c * 16;
            cp16(sb + off,        A + (size_t)(m0 + row) * K + c * 8);
            cp16(sb + GMAT + off, B + (size_t)(n0 + row) * K + c * 8);
        }
    }
    CP_COMMIT();

    for (int ch = 0; ch < NCH; ch++) {
        if (ch + 1 < NCH) {
            uint32_t d = sb + ((ch + 1) & 1) * GSTG;
            int k0 = (ch + 1) << 5;
            #pragma unroll
            for (int i = 0; i < 2; i++) {
                int idx = tid + (i << 8);
                int row = idx >> 2, c = idx & 3;
                uint32_t off = row * GP + c * 16;
                cp16(d + off,        A + (size_t)(m0 + row) * K + k0 + c * 8);
                cp16(d + GMAT + off, B + (size_t)(n0 + row) * K + k0 + c * 8);
            }
        }
        CP_COMMIT();
        CP_WAIT1();
        __syncthreads();

        const uint32_t base = sb + (ch & 1) * GSTG;
        #pragma unroll
        for (int kk = 0; kk < 2; kk++) {
            uint32_t af[2][4];
            #pragma unroll
            for (int sm = 0; sm < 2; sm++) {
                uint32_t aoff = (wm + sm * 16 + arow) * GP + (kk * 16 + akoff) * 2;
                ldsm4(af[sm], base + aoff);
            }
            uint32_t bf4[4][4];
            #pragma unroll
            for (int q = 0; q < 4; q++) {
                uint32_t boff = (wn + q * 16 + brow) * GP + (kk * 16 + bkoff) * 2;
                ldsm4(bf4[q], base + GMAT + boff);
            }
            #pragma unroll
            for (int sm = 0; sm < 2; sm++)
                #pragma unroll
                for (int nt = 0; nt < 8; nt++)
                    mma16816(acc[sm][nt], af[sm], &bf4[nt >> 1][(nt & 1) << 1]);
        }
        __syncthreads();
    }

    const int r0 = wm + (lane >> 2);
    const int c0 = wn + ((lane & 3) << 1);
    #pragma unroll
    for (int sm = 0; sm < 2; sm++)
        #pragma unroll
        for (int nt = 0; nt < 8; nt++) {
            int row = m0 + r0 + sm * 16;
            int col = n0 + c0 + nt * 8;
            if (MODE == 0) {
                *(float2*)(Cf + (size_t)row * N + col) =
                    make_float2(acc[sm][nt][0], acc[sm][nt][1]);
                *(float2*)(Cf + (size_t)(row + 8) * N + col) =
                    make_float2(acc[sm][nt][2], acc[sm][nt][3]);
            } else {
                *(uint32_t*)(Ch + (size_t)row * N + col) =
                    pack2(acc[sm][nt][0] * scale, acc[sm][nt][1] * scale);
                *(uint32_t*)(Ch + (size_t)(row + 8) * N + col) =
                    pack2(acc[sm][nt][2] * scale, acc[sm][nt][3] * scale);
            }
        }
}

// merged q-proj + kv-proj (one launch, no wave tails)
__global__ __launch_bounds__(256, 1)
void proj_gemm(const fp16* __restrict__ qin, const fp16* __restrict__ kvin,
               const fp16* __restrict__ wq, const fp16* __restrict__ wkv,
               fp16* __restrict__ q, fp16* __restrict__ kv) {
    extern __shared__ __align__(128) char smem[];
    const uint32_t sb = smem_u32(smem);
    const int bx = blockIdx.x, m0 = blockIdx.y << 7;
    if (bx < HID / 128) {
        gemm_core<1>(sb, qin, wq, nullptr, q, HID, HID, m0, bx << 7, QSCALE);
    } else {
        gemm_core<1>(sb, kvin, wkv, nullptr, kv, 2 * HID, HID, m0, (bx - HID / 128) << 7, 1.0f);
    }
}

__global__ __launch_bounds__(256, 1)
void out_gemm(const fp16* __restrict__ y, const fp16* __restrict__ wc,
              float* __restrict__ out) {
    extern __shared__ __align__(128) char smem[];
    const uint32_t sb = smem_u32(smem);
    gemm_core<0>(sb, y, wc, out, nullptr, HID, HID, blockIdx.y << 7, blockIdx.x << 7, 0.f);
}

// ================= flash attention on fp16 mma.sync =================
// CTA: 128 queries x one (b,h). 8 warps. 128-row KV iterations, single rescale.
#define AP     144                 // pitch bytes per 64-fp16 row
#define AQMAT  (128 * AP)          // 18432
#define AM2    (128 * AP)          // one K or V matrix (128 rows)
#define ASTG   (2 * AM2)           // K+V per stage = 36864
#define ASMEM  (AQMAT + 2 * ASTG)  // 92160

__global__ __launch_bounds__(256, 1)
void attn_mma(const fp16* __restrict__ q, const fp16* __restrict__ kv,
              fp16* __restrict__ y) {
    extern __shared__ __align__(128) char smem[];
    const uint32_t sb = smem_u32(smem);
    const int tid = threadIdx.x, lane = tid & 31, wid = tid >> 5;
    const int bh = blockIdx.y;
    const int b = bh >> 4, h = bh & 15;
    const int q0 = blockIdx.x << 7;

    const int arow  = (lane & 7) + ((lane >> 3) & 1) * 8;
    const int akoff = ((lane >> 4) << 3);
    const int brow  = (lane & 7) + ((lane >> 4) << 3);
    const int bkoff = ((lane >> 3) & 1) * 8;

    const uint32_t sQ  = sb;
    const uint32_t sKV = sb + AQMAT;

    // --- load Q tile (128 x 64) ---
    #pragma unroll
    for (int i = 0; i < 4; i++) {
        int idx = tid + (i << 8);
        int row = idx >> 3, c = idx & 7;
        cp16(sQ + row * AP + c * 16,
             q + (size_t)(b * SEQ + q0 + row) * HID + h * HEADDIM + c * 8);
    }
    CP_COMMIT();

    // --- preload KV iter 0 (128 rows of K and V) ---
    const size_t kvrow0 = (size_t)(b * SEQ);
    #pragma unroll
    for (int i = 0; i < 4; i++) {
        int idx = tid + (i << 8);
        int row = idx >> 3, c = idx & 7;
        uint32_t off = row * AP + c * 16;
        size_t gk = (kvrow0 + row) * (2 * HID) + h * HEADDIM + c * 8;
        cp16(sKV + off,       kv + gk);
        cp16(sKV + AM2 + off, kv + gk + HID);
    }
    CP_COMMIT();
    CP_WAIT1();        // Q resident
    __syncthreads();

    uint32_t qf[4][4];
    #pragma unroll
    for (int kk = 0; kk < 4; kk++)
        ldsm4(qf[kk], sQ + (wid * 16 + arow) * AP + (kk * 16 + akoff) * 2);

    float o[8][4];
    #pragma unroll
    for (int i = 0; i < 8; i++)
        #pragma unroll
        for (int r = 0; r < 4; r++) o[i][r] = 0.f;
    float m0_ = -INFINITY, m1_ = -INFINITY, l0_ = 0.f, l1_ = 0.f;

    const int NIT = SEQ / 128;
    for (int ch = 0; ch < NIT; ch++) {
        if (ch + 1 < NIT) {
            uint32_t d = sKV + ((ch + 1) & 1) * ASTG;
            int t0 = (ch + 1) << 7;
            #pragma unroll
            for (int i = 0; i < 4; i++) {
                int idx = tid + (i << 8);
                int row = idx >> 3, c = idx & 7;
                uint32_t off = row * AP + c * 16;
                size_t gk = (kvrow0 + t0 + row) * (2 * HID) + h * HEADDIM + c * 8;
                cp16(d + off,       kv + gk);
                cp16(d + AM2 + off, kv + gk + HID);
            }
        }
        CP_COMMIT();
        CP_WAIT1();
        __syncthreads();

        const uint32_t sK = sKV + (ch & 1) * ASTG;
        const uint32_t sV = sK + AM2;

        // ---- S_A (keys 0-63), S_B (keys 64-127) ----
        float sA[8][4], sB[8][4];
        #pragma unroll
        for (int i = 0; i < 8; i++)
            #pragma unroll
            for (int r = 0; r < 4; r++) { sA[i][r] = 0.f; sB[i][r] = 0.f; }

        #pragma unroll
        for (int kk = 0; kk < 4; kk++) {
            uint32_t kb[4][4];
            #pragma unroll
            for (int g = 0; g < 4; g++)
                ldsm4(kb[g], sK + (g * 16 + brow) * AP + (kk * 16 + bkoff) * 2);
            #pragma unroll
            for (int nt = 0; nt < 8; nt++)
                mma16816(sA[nt], qf[kk], &kb[nt >> 1][(nt & 1) << 1]);
        }
        #pragma unroll
        for (int kk = 0; kk < 4; kk++) {
            uint32_t kb[4][4];
            #pragma unroll
            for (int g = 0; g < 4; g++)
                ldsm4(kb[g], sK + ((64 + g * 16) + brow) * AP + (kk * 16 + bkoff) * 2);
            #pragma unroll
            for (int nt = 0; nt < 8; nt++)
                mma16816(sB[nt], qf[kk], &kb[nt >> 1][(nt & 1) << 1]);
        }

        // ---- single online-softmax update over 128 keys ----
        float mx0 = -INFINITY, mx1 = -INFINITY;
        #pragma unroll
        for (int nt = 0; nt < 8; nt++) {
            mx0 = fmaxf(mx0, fmaxf(fmaxf(sA[nt][0], sA[nt][1]), fmaxf(sB[nt][0], sB[nt][1])));
            mx1 = fmaxf(mx1, fmaxf(fmaxf(sA[nt][2], sA[nt][3]), fmaxf(sB[nt][2], sB[nt][3])));
        }
        mx0 = fmaxf(mx0, __shfl_xor_sync(0xffffffffu, mx0, 1));
        mx0 = fmaxf(mx0, __shfl_xor_sync(0xffffffffu, mx0, 2));
        mx1 = fmaxf(mx1, __shfl_xor_sync(0xffffffffu, mx1, 1));
        mx1 = fmaxf(mx1, __shfl_xor_sync(0xffffffffu, mx1, 2));
        float mn0 = fmaxf(m0_, mx0), mn1 = fmaxf(m1_, mx1);
        float corr0 = exp2f(m0_ - mn0), corr1 = exp2f(m1_ - mn1);
        m0_ = mn0; m1_ = mn1;

        float rs0 = 0.f, rs1 = 0.f;
        uint32_t phA[4][4];
        #pragma unroll
        for (int nt = 0; nt < 8; nt++) {
            sA[nt][0] = exp2f(sA[nt][0] - mn0); rs0 += sA[nt][0];
            sA[nt][1] = exp2f(sA[nt][1] - mn0); rs0 += sA[nt][1];
            sA[nt][2] = exp2f(sA[nt][2] - mn1); rs1 += sA[nt][2];
            sA[nt][3] = exp2f(sA[nt][3] - mn1); rs1 += sA[nt][3];
        }
        #pragma unroll
        for (int j = 0; j < 4; j++) {
            phA[j][0] = pack2(sA[2*j][0], sA[2*j][1]);
            phA[j][1] = pack2(sA[2*j][2], sA[2*j][3]);
            phA[j][2] = pack2(sA[2*j+1][0], sA[2*j+1][1]);
            phA[j][3] = pack2(sA[2*j+1][2], sA[2*j+1][3]);
        }

        #pragma unroll
        for (int dt = 0; dt < 8; dt++) {
            o[dt][0] *= corr0; o[dt][1] *= corr0;
            o[dt][2] *= corr1; o[dt][3] *= corr1;
        }

        // ---- PV(A); softmax(B) ALU interleaves with these MMAs ----
        #pragma unroll
        for (int j = 0; j < 4; j++) {
            uint32_t vb[4][4];
            #pragma unroll
            for (int dq = 0; dq < 4; dq++)
                ldsm4t(vb[dq], sV + (j * 16 + arow) * AP + (dq * 16 + akoff) * 2);
            #pragma unroll
            for (int dt = 0; dt < 8; dt++)
                mma16816(o[dt], phA[j], &vb[dt >> 1][(dt & 1) << 1]);
        }

        uint32_t phB[4][4];
        #pragma unroll
        for (int nt = 0; nt < 8; nt++) {
            sB[nt][0] = exp2f(sB[nt][0] - mn0); rs0 += sB[nt][0];
            sB[nt][1] = exp2f(sB[nt][1] - mn0); rs0 += sB[nt][1];
            sB[nt][2] = exp2f(sB[nt][2] - mn1); rs1 += sB[nt][2];
            sB[nt][3] = exp2f(sB[nt][3] - mn1); rs1 += sB[nt][3];
        }
        #pragma unroll
        for (int j = 0; j < 4; j++) {
            phB[j][0] = pack2(sB[2*j][0], sB[2*j][1]);
            phB[j][1] = pack2(sB[2*j][2], sB[2*j][3]);
            phB[j][2] = pack2(sB[2*j+1][0], sB[2*j+1][1]);
            phB[j][3] = pack2(sB[2*j+1][2], sB[2*j+1][3]);
        }

        rs0 += __shfl_xor_sync(0xffffffffu, rs0, 1);
        rs0 += __shfl_xor_sync(0xffffffffu, rs0, 2);
        rs1 += __shfl_xor_sync(0xffffffffu, rs1, 1);
        rs1 += __shfl_xor_sync(0xffffffffu, rs1, 2);
        l0_ = l0_ * corr0 + rs0;
        l1_ = l1_ * corr1 + rs1;

        // ---- PV(B) ----
        #pragma unroll
        for (int j = 0; j < 4; j++) {
            uint32_t vb[4][4];
            #pragma unroll
            for (int dq = 0; dq < 4; dq++)
                ldsm4t(vb[dq], sV + ((64 + j * 16) + arow) * AP + (dq * 16 + akoff) * 2);
            #pragma unroll
            for (int dt = 0; dt < 8; dt++)
                mma16816(o[dt], phB[j], &vb[dt >> 1][(dt & 1) << 1]);
        }
        __syncthreads();
    }

    // ---- epilogue: normalize, store y (fp16) ----
    const float inv0 = 1.f / l0_, inv1 = 1.f / l1_;
    const int gr = b * SEQ + q0 + wid * 16 + (lane >> 2);
    const int col = h * HEADDIM + ((lane & 3) << 1);
    #pragma unroll
    for (int dt = 0; dt < 8; dt++) {
        *(uint32_t*)(y + (size_t)gr * HID + col + dt * 8) =
            pack2(o[dt][0] * inv0, o[dt][1] * inv0);
        *(uint32_t*)(y + (size_t)(gr + 8) * HID + col + dt * 8) =
            pack2(o[dt][2] * inv1, o[dt][3] * inv1);
    }
}

// ---------------- converters ----------------
__global__ void convert_act(const float* __restrict__ in, fp16* __restrict__ h, int n) {
    int i = (blockIdx.x * blockDim.x + threadIdx.x) << 2;
    if (i >= n) return;
    float4 v = *(const float4*)(in + i);
    *(uint32_t*)(h + i)     = pack2(v.x, v.y);
    *(uint32_t*)(h + i + 2) = pack2(v.z, v.w);
}

// W[K,N'] fp32 -> T[N,K] fp16 (transpose); pass pre-offset W pointer, N = full row stride
__global__ void trconv(const float* __restrict__ W, fp16* __restrict__ T, int K, int N) {
    __shared__ float t[32][33];
    const int n0 = blockIdx.x << 5, k0 = blockIdx.y << 5;
    const int tx = threadIdx.x, ty = threadIdx.y;
    #pragma unroll
    for (int j = 0; j < 32; j += 8)
        t[ty + j][tx] = W[(size_t)(k0 + ty + j) * N + n0 + tx];
    __syncthreads();
    #pragma unroll
    for (int j = 0; j < 32; j += 8)
        T[(size_t)(n0 + ty + j) * K + k0 + tx] = __float2half(t[tx][ty + j]);
}

// ---------------- launch ----------------
extern "C" void kernel_launch(void* const* d_in, const int* in_sizes, int n_in,
                              void* d_out, int out_size) {
    const float* query     = (const float*)d_in[0];
    const float* key_value = (const float*)d_in[1];
    const float* Wq        = (const float*)d_in[2];
    const float* Wkv       = (const float*)d_in[3];
    const float* Wc        = (const float*)d_in[4];
    float* out = (float*)d_out;

    fp16 *qin, *kvin, *q, *kv, *y, *wqT, *wkvT, *wcT;
    cudaGetSymbolAddress((void**)&qin,  g_qin);
    cudaGetSymbolAddress((void**)&kvin, g_kvin);
    cudaGetSymbolAddress((void**)&q,    g_q);
    cudaGetSymbolAddress((void**)&kv,   g_kv);
    cudaGetSymbolAddress((void**)&y,    g_y);
    cudaGetSymbolAddress((void**)&wqT,  g_wqT);
    cudaGetSymbolAddress((void**)&wkvT, g_wkvT);
    cudaGetSymbolAddress((void**)&wcT,  g_wcT);

    cudaFuncSetAttribute(proj_gemm, cudaFuncAttributeMaxDynamicSharedMemorySize, GSMEM);
    cudaFuncSetAttribute(out_gemm,  cudaFuncAttributeMaxDynamicSharedMemorySize, GSMEM);
    cudaFuncSetAttribute(attn_mma,  cudaFuncAttributeMaxDynamicSharedMemorySize, ASMEM);

    // convert inputs + weights to fp16
    convert_act<<<MROWS * HID / 4 / 256, 256>>>(query, qin, MROWS * HID);
    convert_act<<<MROWS * HID / 4 / 256, 256>>>(key_value, kvin, MROWS * HID);
    trconv<<<dim3(HID / 32, HID / 32),     dim3(32, 8)>>>(Wq,  wqT,  HID, HID);
    trconv<<<dim3(2 * HID / 32, HID / 32), dim3(32, 8)>>>(Wkv, wkvT, HID, 2 * HID);
    trconv<<<dim3(HID / 32, HID / 32),     dim3(32, 8)>>>(Wc,  wcT,  HID, HID);

    // merged projections: bx<8 -> q-proj (QSCALE folded), else kv-proj
    proj_gemm<<<dim3(HID / 128 + 2 * HID / 128, MROWS / 128), 256, GSMEM>>>(
        qin, kvin, wqT, wkvT, q, kv);

    attn_mma<<<dim3(SEQ / 128, BATCH * NHEADS), 256, ASMEM>>>(q, kv, y);

    out_gemm<<<dim3(HID / 128, MROWS / 128), 256, GSMEM>>>(y, wcT, out);
}

// round 15
// speedup vs baseline: 4.0966x; 1.8507x over previous
#include <cuda_runtime.h>
#include <cuda_fp16.h>
#include <math.h>
#include <stdint.h>

#define HID 1024
#define NHEADS 16
#define HEADDIM 64
#define BATCH 2
#define SEQ 2048
#define MROWS (BATCH * SEQ)   // 4096

#define QSCALE (0.125f * 1.4426950408889634f)   // 1/sqrt(64) * log2(e), folded into q

typedef __half fp16;

// ---------------- scratch ----------------
__device__ fp16 g_qin [(size_t)MROWS * HID];
__device__ fp16 g_kvin[(size_t)MROWS * HID];
__device__ fp16 g_q   [(size_t)MROWS * HID];
__device__ fp16 g_kv  [(size_t)MROWS * 2 * HID];
__device__ fp16 g_y   [(size_t)MROWS * HID];
__device__ fp16 g_wqT [(size_t)HID * HID];
__device__ fp16 g_wkvT[(size_t)2 * HID * HID];
__device__ fp16 g_wcT [(size_t)HID * HID];

// ---------------- PTX helpers ----------------
__device__ __forceinline__ uint32_t smem_u32(const void* p) {
    uint32_t a;
    asm("{ .reg .u64 t; cvta.to.shared.u64 t, %1; cvt.u32.u64 %0, t; }" : "=r"(a) : "l"(p));
    return a;
}
__device__ __forceinline__ void cp16(uint32_t s, const void* g) {
    asm volatile("cp.async.cg.shared.global [%0], [%1], 16;" :: "r"(s), "l"(g));
}
#define CP_COMMIT() asm volatile("cp.async.commit_group;" ::: "memory")
#define CP_WAIT1()  asm volatile("cp.async.wait_group 1;" ::: "memory")

__device__ __forceinline__ void ldsm4(uint32_t* r, uint32_t a) {
    asm volatile("ldmatrix.sync.aligned.m8n8.x4.shared.b16 {%0,%1,%2,%3}, [%4];"
                 : "=r"(r[0]), "=r"(r[1]), "=r"(r[2]), "=r"(r[3]) : "r"(a));
}
__device__ __forceinline__ void ldsm4t(uint32_t* r, uint32_t a) {
    asm volatile("ldmatrix.sync.aligned.m8n8.x4.trans.shared.b16 {%0,%1,%2,%3}, [%4];"
                 : "=r"(r[0]), "=r"(r[1]), "=r"(r[2]), "=r"(r[3]) : "r"(a));
}
__device__ __forceinline__ void mma16816(float* d, const uint32_t* a, const uint32_t* b) {
    asm volatile(
        "mma.sync.aligned.m16n8k16.row.col.f32.f16.f16.f32 "
        "{%0,%1,%2,%3}, {%4,%5,%6,%7}, {%8,%9}, {%0,%1,%2,%3};"
        : "+f"(d[0]), "+f"(d[1]), "+f"(d[2]), "+f"(d[3])
        : "r"(a[0]), "r"(a[1]), "r"(a[2]), "r"(a[3]), "r"(b[0]), "r"(b[1]));
}

__device__ __forceinline__ uint32_t pack2(float a, float b) {
    __half2 t = __floats2half2_rn(a, b);
    return *(uint32_t*)&t;
}

// ================= fp16 mma.sync GEMM core =================
// C[M,N] = A[M,K] . B^T, B stored [N,K] row-major (pre-transposed).
// CTA tile 128x128, BK=32, 8 warps (4m x 2n), warp tile 32x64. 2 CTAs/SM.
#define GP    80      // smem pitch bytes per 32-fp16 row
#define GMAT  10240   // 128 rows * 80B
#define GSTG  (2 * GMAT)      // A + B per stage = 20480
#define GSMEM (2 * GSTG)      // 40960

template<int MODE>   // 0: fp32 out, 1: fp16 out (scaled)
__device__ __forceinline__ void gemm_core(
    uint32_t sb,
    const fp16* __restrict__ A, const fp16* __restrict__ B,
    float* __restrict__ Cf, fp16* __restrict__ Ch,
    int N, int K, int m0, int n0, float scale) {
    const int tid = threadIdx.x, lane = tid & 31, wid = tid >> 5;
    const int wm = (wid >> 1) << 5, wn = (wid & 1) << 6;

    const int arow  = (lane & 7) + ((lane >> 3) & 1) * 8;
    const int akoff = ((lane >> 4) << 3);
    const int brow  = (lane & 7) + ((lane >> 4) << 3);
    const int bkoff = ((lane >> 3) & 1) * 8;

    float acc[2][8][4];
    #pragma unroll
    for (int i = 0; i < 2; i++)
        #pragma unroll
        for (int j = 0; j < 8; j++)
            #pragma unroll
            for (int r = 0; r < 4; r++) acc[i][j][r] = 0.f;

    const int NCH = K >> 5;

    {   // preload chunk 0
        #pragma unroll
        for (int i = 0; i < 2; i++) {
            int idx = tid + (i << 8);
            int row = idx >> 2, c = idx & 3;
            uint32_t off = row * GP + c * 16;
            cp16(sb + off,        A + (size_t)(m0 + row) * K + c * 8);
            cp16(sb + GMAT + off, B + (size_t)(n0 + row) * K + c * 8);
        }
    }
    CP_COMMIT();

    for (int ch = 0; ch < NCH; ch++) {
        if (ch + 1 < NCH) {
            uint32_t d = sb + ((ch + 1) & 1) * GSTG;
            int k0 = (ch + 1) << 5;
            #pragma unroll
            for (int i = 0; i < 2; i++) {
                int idx = tid + (i << 8);
                int row = idx >> 2, c = idx & 3;
                uint32_t off = row * GP + c * 16;
                cp16(d + off,        A + (size_t)(m0 + row) * K + k0 + c * 8);
                cp16(d + GMAT + off, B + (size_t)(n0 + row) * K + k0 + c * 8);
            }
        }
        CP_COMMIT();
        CP_WAIT1();
        __syncthreads();

        const uint32_t base = sb + (ch & 1) * GSTG;
        #pragma unroll
        for (int kk = 0; kk < 2; kk++) {
            uint32_t af[2][4];
            #pragma unroll
            for (int sm = 0; sm < 2; sm++) {
                uint32_t aoff = (wm + sm * 16 + arow) * GP + (kk * 16 + akoff) * 2;
                ldsm4(af[sm], base + aoff);
            }
            uint32_t bf4[4][4];
            #pragma unroll
            for (int q = 0; q < 4; q++) {
                uint32_t boff = (wn + q * 16 + brow) * GP + (kk * 16 + bkoff) * 2;
                ldsm4(bf4[q], base + GMAT + boff);
            }
            #pragma unroll
            for (int sm = 0; sm < 2; sm++)
                #pragma unroll
                for (int nt = 0; nt < 8; nt++)
                    mma16816(acc[sm][nt], af[sm], &bf4[nt >> 1][(nt & 1) << 1]);
        }
        __syncthreads();
    }

    const int r0 = wm + (lane >> 2);
    const int c0 = wn + ((lane & 3) << 1);
    #pragma unroll
    for (int sm = 0; sm < 2; sm++)
        #pragma unroll
        for (int nt = 0; nt < 8; nt++) {
            int row = m0 + r0 + sm * 16;
            int col = n0 + c0 + nt * 8;
            if (MODE == 0) {
                *(float2*)(Cf + (size_t)row * N + col) =
                    make_float2(acc[sm][nt][0], acc[sm][nt][1]);
                *(float2*)(Cf + (size_t)(row + 8) * N + col) =
                    make_float2(acc[sm][nt][2], acc[sm][nt][3]);
            } else {
                *(uint32_t*)(Ch + (size_t)row * N + col) =
                    pack2(acc[sm][nt][0] * scale, acc[sm][nt][1] * scale);
                *(uint32_t*)(Ch + (size_t)(row + 8) * N + col) =
                    pack2(acc[sm][nt][2] * scale, acc[sm][nt][3] * scale);
            }
        }
}

// merged q-proj + kv-proj (one launch, no wave tails)
__global__ __launch_bounds__(256, 2)
void proj_gemm(const fp16* __restrict__ qin, const fp16* __restrict__ kvin,
               const fp16* __restrict__ wq, const fp16* __restrict__ wkv,
               fp16* __restrict__ q, fp16* __restrict__ kv) {
    extern __shared__ __align__(128) char smem[];
    const uint32_t sb = smem_u32(smem);
    const int bx = blockIdx.x, m0 = blockIdx.y << 7;
    if (bx < HID / 128) {
        gemm_core<1>(sb, qin, wq, nullptr, q, HID, HID, m0, bx << 7, QSCALE);
    } else {
        gemm_core<1>(sb, kvin, wkv, nullptr, kv, 2 * HID, HID, m0, (bx - HID / 128) << 7, 1.0f);
    }
}

__global__ __launch_bounds__(256, 2)
void out_gemm(const fp16* __restrict__ y, const fp16* __restrict__ wc,
              float* __restrict__ out) {
    extern __shared__ __align__(128) char smem[];
    const uint32_t sb = smem_u32(smem);
    gemm_core<0>(sb, y, wc, out, nullptr, HID, HID, blockIdx.y << 7, blockIdx.x << 7, 0.f);
}

// ================= flash attention on fp16 mma.sync =================
// CTA: 64 queries x one (b,h), 128 threads / 4 warps (16 q-rows per warp).
// 128-row KV iterations, single rescale. 2 CTAs/SM (regs ~185*128=23.7K, smem 83KB).
#define AP     144                 // pitch bytes per 64-fp16 row
#define AQMAT  (64 * AP)           // 9216  (Q tile: 64 rows)
#define AM2    (128 * AP)          // one K or V matrix (128 rows) = 18432
#define ASTG   (2 * AM2)           // K+V per stage = 36864
#define ASMEM  (AQMAT + 2 * ASTG)  // 82944

__global__ __launch_bounds__(128, 2)
void attn_mma(const fp16* __restrict__ q, const fp16* __restrict__ kv,
              fp16* __restrict__ y) {
    extern __shared__ __align__(128) char smem[];
    const uint32_t sb = smem_u32(smem);
    const int tid = threadIdx.x, lane = tid & 31, wid = tid >> 5;
    const int bh = blockIdx.y;
    const int b = bh >> 4, h = bh & 15;
    const int q0 = blockIdx.x << 6;      // 64-query tiles

    const int arow  = (lane & 7) + ((lane >> 3) & 1) * 8;
    const int akoff = ((lane >> 4) << 3);
    const int brow  = (lane & 7) + ((lane >> 4) << 3);
    const int bkoff = ((lane >> 3) & 1) * 8;

    const uint32_t sQ  = sb;
    const uint32_t sKV = sb + AQMAT;

    // --- load Q tile (64 x 64): 512 cp16 ops, 128 threads x 4 ---
    #pragma unroll
    for (int i = 0; i < 4; i++) {
        int idx = tid + (i << 7);
        int row = idx >> 3, c = idx & 7;
        cp16(sQ + row * AP + c * 16,
             q + (size_t)(b * SEQ + q0 + row) * HID + h * HEADDIM + c * 8);
    }
    CP_COMMIT();

    // --- preload KV iter 0 (128 rows of K and V): 8 x (K,V) per thread ---
    const size_t kvrow0 = (size_t)(b * SEQ);
    #pragma unroll
    for (int i = 0; i < 8; i++) {
        int idx = tid + (i << 7);
        int row = idx >> 3, c = idx & 7;
        uint32_t off = row * AP + c * 16;
        size_t gk = (kvrow0 + row) * (2 * HID) + h * HEADDIM + c * 8;
        cp16(sKV + off,       kv + gk);
        cp16(sKV + AM2 + off, kv + gk + HID);
    }
    CP_COMMIT();
    CP_WAIT1();        // Q resident
    __syncthreads();

    uint32_t qf[4][4];
    #pragma unroll
    for (int kk = 0; kk < 4; kk++)
        ldsm4(qf[kk], sQ + (wid * 16 + arow) * AP + (kk * 16 + akoff) * 2);

    float o[8][4];
    #pragma unroll
    for (int i = 0; i < 8; i++)
        #pragma unroll
        for (int r = 0; r < 4; r++) o[i][r] = 0.f;
    float m0_ = -INFINITY, m1_ = -INFINITY, l0_ = 0.f, l1_ = 0.f;

    const int NIT = SEQ / 128;
    for (int ch = 0; ch < NIT; ch++) {
        if (ch + 1 < NIT) {
            uint32_t d = sKV + ((ch + 1) & 1) * ASTG;
            int t0 = (ch + 1) << 7;
            #pragma unroll
            for (int i = 0; i < 8; i++) {
                int idx = tid + (i << 7);
                int row = idx >> 3, c = idx & 7;
                uint32_t off = row * AP + c * 16;
                size_t gk = (kvrow0 + t0 + row) * (2 * HID) + h * HEADDIM + c * 8;
                cp16(d + off,       kv + gk);
                cp16(d + AM2 + off, kv + gk + HID);
            }
        }
        CP_COMMIT();
        CP_WAIT1();
        __syncthreads();

        const uint32_t sK = sKV + (ch & 1) * ASTG;
        const uint32_t sV = sK + AM2;

        // ---- S_A (keys 0-63), S_B (keys 64-127) ----
        float sA[8][4], sB[8][4];
        #pragma unroll
        for (int i = 0; i < 8; i++)
            #pragma unroll
            for (int r = 0; r < 4; r++) { sA[i][r] = 0.f; sB[i][r] = 0.f; }

        #pragma unroll
        for (int kk = 0; kk < 4; kk++) {
            uint32_t kb[4][4];
            #pragma unroll
            for (int g = 0; g < 4; g++)
                ldsm4(kb[g], sK + (g * 16 + brow) * AP + (kk * 16 + bkoff) * 2);
            #pragma unroll
            for (int nt = 0; nt < 8; nt++)
                mma16816(sA[nt], qf[kk], &kb[nt >> 1][(nt & 1) << 1]);
        }
        #pragma unroll
        for (int kk = 0; kk < 4; kk++) {
            uint32_t kb[4][4];
            #pragma unroll
            for (int g = 0; g < 4; g++)
                ldsm4(kb[g], sK + ((64 + g * 16) + brow) * AP + (kk * 16 + bkoff) * 2);
            #pragma unroll
            for (int nt = 0; nt < 8; nt++)
                mma16816(sB[nt], qf[kk], &kb[nt >> 1][(nt & 1) << 1]);
        }

        // ---- single online-softmax update over 128 keys ----
        float mx0 = -INFINITY, mx1 = -INFINITY;
        #pragma unroll
        for (int nt = 0; nt < 8; nt++) {
            mx0 = fmaxf(mx0, fmaxf(fmaxf(sA[nt][0], sA[nt][1]), fmaxf(sB[nt][0], sB[nt][1])));
            mx1 = fmaxf(mx1, fmaxf(fmaxf(sA[nt][2], sA[nt][3]), fmaxf(sB[nt][2], sB[nt][3])));
        }
        mx0 = fmaxf(mx0, __shfl_xor_sync(0xffffffffu, mx0, 1));
        mx0 = fmaxf(mx0, __shfl_xor_sync(0xffffffffu, mx0, 2));
        mx1 = fmaxf(mx1, __shfl_xor_sync(0xffffffffu, mx1, 1));
        mx1 = fmaxf(mx1, __shfl_xor_sync(0xffffffffu, mx1, 2));
        float mn0 = fmaxf(m0_, mx0), mn1 = fmaxf(m1_, mx1);
        float corr0 = exp2f(m0_ - mn0), corr1 = exp2f(m1_ - mn1);
        m0_ = mn0; m1_ = mn1;

        float rs0 = 0.f, rs1 = 0.f;
        uint32_t phA[4][4];
        #pragma unroll
        for (int nt = 0; nt < 8; nt++) {
            sA[nt][0] = exp2f(sA[nt][0] - mn0); rs0 += sA[nt][0];
            sA[nt][1] = exp2f(sA[nt][1] - mn0); rs0 += sA[nt][1];
            sA[nt][2] = exp2f(sA[nt][2] - mn1); rs1 += sA[nt][2];
            sA[nt][3] = exp2f(sA[nt][3] - mn1); rs1 += sA[nt][3];
        }
        #pragma unroll
        for (int j = 0; j < 4; j++) {
            phA[j][0] = pack2(sA[2*j][0], sA[2*j][1]);
            phA[j][1] = pack2(sA[2*j][2], sA[2*j][3]);
            phA[j][2] = pack2(sA[2*j+1][0], sA[2*j+1][1]);
            phA[j][3] = pack2(sA[2*j+1][2], sA[2*j+1][3]);
        }

        #pragma unroll
        for (int dt = 0; dt < 8; dt++) {
            o[dt][0] *= corr0; o[dt][1] *= corr0;
            o[dt][2] *= corr1; o[dt][3] *= corr1;
        }

        // ---- PV(A); softmax(B) ALU interleaves with these MMAs ----
        #pragma unroll
        for (int j = 0; j < 4; j++) {
            uint32_t vb[4][4];
            #pragma unroll
            for (int dq = 0; dq < 4; dq++)
                ldsm4t(vb[dq], sV + (j * 16 + arow) * AP + (dq * 16 + akoff) * 2);
            #pragma unroll
            for (int dt = 0; dt < 8; dt++)
                mma16816(o[dt], phA[j], &vb[dt >> 1][(dt & 1) << 1]);
        }

        uint32_t phB[4][4];
        #pragma unroll
        for (int nt = 0; nt < 8; nt++) {
            sB[nt][0] = exp2f(sB[nt][0] - mn0); rs0 += sB[nt][0];
            sB[nt][1] = exp2f(sB[nt][1] - mn0); rs0 += sB[nt][1];
            sB[nt][2] = exp2f(sB[nt][2] - mn1); rs1 += sB[nt][2];
            sB[nt][3] = exp2f(sB[nt][3] - mn1); rs1 += sB[nt][3];
        }
        #pragma unroll
        for (int j = 0; j < 4; j++) {
            phB[j][0] = pack2(sB[2*j][0], sB[2*j][1]);
            phB[j][1] = pack2(sB[2*j][2], sB[2*j][3]);
            phB[j][2] = pack2(sB[2*j+1][0], sB[2*j+1][1]);
            phB[j][3] = pack2(sB[2*j+1][2], sB[2*j+1][3]);
        }

        rs0 += __shfl_xor_sync(0xffffffffu, rs0, 1);
        rs0 += __shfl_xor_sync(0xffffffffu, rs0, 2);
        rs1 += __shfl_xor_sync(0xffffffffu, rs1, 1);
        rs1 += __shfl_xor_sync(0xffffffffu, rs1, 2);
        l0_ = l0_ * corr0 + rs0;
        l1_ = l1_ * corr1 + rs1;

        // ---- PV(B) ----
        #pragma unroll
        for (int j = 0; j < 4; j++) {
            uint32_t vb[4][4];
            #pragma unroll
            for (int dq = 0; dq < 4; dq++)
                ldsm4t(vb[dq], sV + ((64 + j * 16) + arow) * AP + (dq * 16 + akoff) * 2);
            #pragma unroll
            for (int dt = 0; dt < 8; dt++)
                mma16816(o[dt], phB[j], &vb[dt >> 1][(dt & 1) << 1]);
        }
        __syncthreads();
    }

    // ---- epilogue: normalize, store y (fp16) ----
    const float inv0 = 1.f / l0_, inv1 = 1.f / l1_;
    const int gr = b * SEQ + q0 + wid * 16 + (lane >> 2);
    const int col = h * HEADDIM + ((lane & 3) << 1);
    #pragma unroll
    for (int dt = 0; dt < 8; dt++) {
        *(uint32_t*)(y + (size_t)gr * HID + col + dt * 8) =
            pack2(o[dt][0] * inv0, o[dt][1] * inv0);
        *(uint32_t*)(y + (size_t)(gr + 8) * HID + col + dt * 8) =
            pack2(o[dt][2] * inv1, o[dt][3] * inv1);
    }
}

// ---------------- converters ----------------
__global__ void convert_act(const float* __restrict__ in, fp16* __restrict__ h, int n) {
    int i = (blockIdx.x * blockDim.x + threadIdx.x) << 2;
    if (i >= n) return;
    float4 v = *(const float4*)(in + i);
    *(uint32_t*)(h + i)     = pack2(v.x, v.y);
    *(uint32_t*)(h + i + 2) = pack2(v.z, v.w);
}

// W[K,N'] fp32 -> T[N,K] fp16 (transpose); pass pre-offset W pointer, N = full row stride
__global__ void trconv(const float* __restrict__ W, fp16* __restrict__ T, int K, int N) {
    __shared__ float t[32][33];
    const int n0 = blockIdx.x << 5, k0 = blockIdx.y << 5;
    const int tx = threadIdx.x, ty = threadIdx.y;
    #pragma unroll
    for (int j = 0; j < 32; j += 8)
        t[ty + j][tx] = W[(size_t)(k0 + ty + j) * N + n0 + tx];
    __syncthreads();
    #pragma unroll
    for (int j = 0; j < 32; j += 8)
        T[(size_t)(n0 + ty + j) * K + k0 + tx] = __float2half(t[tx][ty + j]);
}

// ---------------- launch ----------------
extern "C" void kernel_launch(void* const* d_in, const int* in_sizes, int n_in,
                              void* d_out, int out_size) {
    const float* query     = (const float*)d_in[0];
    const float* key_value = (const float*)d_in[1];
    const float* Wq        = (const float*)d_in[2];
    const float* Wkv       = (const float*)d_in[3];
    const float* Wc        = (const float*)d_in[4];
    float* out = (float*)d_out;

    fp16 *qin, *kvin, *q, *kv, *y, *wqT, *wkvT, *wcT;
    cudaGetSymbolAddress((void**)&qin,  g_qin);
    cudaGetSymbolAddress((void**)&kvin, g_kvin);
    cudaGetSymbolAddress((void**)&q,    g_q);
    cudaGetSymbolAddress((void**)&kv,   g_kv);
    cudaGetSymbolAddress((void**)&y,    g_y);
    cudaGetSymbolAddress((void**)&wqT,  g_wqT);
    cudaGetSymbolAddress((void**)&wkvT, g_wkvT);
    cudaGetSymbolAddress((void**)&wcT,  g_wcT);

    cudaFuncSetAttribute(proj_gemm, cudaFuncAttributeMaxDynamicSharedMemorySize, GSMEM);
    cudaFuncSetAttribute(out_gemm,  cudaFuncAttributeMaxDynamicSharedMemorySize, GSMEM);
    cudaFuncSetAttribute(attn_mma,  cudaFuncAttributeMaxDynamicSharedMemorySize, ASMEM);

    // convert inputs + weights to fp16
    convert_act<<<MROWS * HID / 4 / 256, 256>>>(query, qin, MROWS * HID);
    convert_act<<<MROWS * HID / 4 / 256, 256>>>(key_value, kvin, MROWS * HID);
    trconv<<<dim3(HID / 32, HID / 32),     dim3(32, 8)>>>(Wq,  wqT,  HID, HID);
    trconv<<<dim3(2 * HID / 32, HID / 32), dim3(32, 8)>>>(Wkv, wkvT, HID, 2 * HID);
    trconv<<<dim3(HID / 32, HID / 32),     dim3(32, 8)>>>(Wc,  wcT,  HID, HID);

    // merged projections: bx<8 -> q-proj (QSCALE folded), else kv-proj
    proj_gemm<<<dim3(HID / 128 + 2 * HID / 128, MROWS / 128), 256, GSMEM>>>(
        qin, kvin, wqT, wkvT, q, kv);

    // attention: 64-query CTAs, 128 threads, 2 CTAs/SM
    attn_mma<<<dim3(SEQ / 64, BATCH * NHEADS), 128, ASMEM>>>(q, kv, y);

    out_gemm<<<dim3(HID / 128, MROWS / 128), 256, GSMEM>>>(y, wcT, out);
}

// round 16
// speedup vs baseline: 4.3756x; 1.0681x over previous
#include <cuda_runtime.h>
#include <cuda_fp16.h>
#include <math.h>
#include <stdint.h>

#define HID 1024
#define NHEADS 16
#define HEADDIM 64
#define BATCH 2
#define SEQ 2048
#define MROWS (BATCH * SEQ)   // 4096

#define QSCALE (0.125f * 1.4426950408889634f)   // 1/sqrt(64) * log2(e), folded into q

typedef __half fp16;

// ---------------- scratch ----------------
__device__ fp16 g_qin [(size_t)MROWS * HID];
__device__ fp16 g_kvin[(size_t)MROWS * HID];
__device__ fp16 g_q   [(size_t)MROWS * HID];
__device__ fp16 g_kv  [(size_t)MROWS * 2 * HID];
__device__ fp16 g_y   [(size_t)MROWS * HID];
__device__ fp16 g_wqT [(size_t)HID * HID];
__device__ fp16 g_wkvT[(size_t)2 * HID * HID];
__device__ fp16 g_wcT [(size_t)HID * HID];

// ---------------- PTX helpers ----------------
__device__ __forceinline__ uint32_t smem_u32(const void* p) {
    uint32_t a;
    asm("{ .reg .u64 t; cvta.to.shared.u64 t, %1; cvt.u32.u64 %0, t; }" : "=r"(a) : "l"(p));
    return a;
}
__device__ __forceinline__ void cp16(uint32_t s, const void* g) {
    asm volatile("cp.async.cg.shared.global [%0], [%1], 16;" :: "r"(s), "l"(g));
}
#define CP_COMMIT() asm volatile("cp.async.commit_group;" ::: "memory")
#define CP_WAIT1()  asm volatile("cp.async.wait_group 1;" ::: "memory")

__device__ __forceinline__ void ldsm4(uint32_t* r, uint32_t a) {
    asm volatile("ldmatrix.sync.aligned.m8n8.x4.shared.b16 {%0,%1,%2,%3}, [%4];"
                 : "=r"(r[0]), "=r"(r[1]), "=r"(r[2]), "=r"(r[3]) : "r"(a));
}
__device__ __forceinline__ void ldsm4t(uint32_t* r, uint32_t a) {
    asm volatile("ldmatrix.sync.aligned.m8n8.x4.trans.shared.b16 {%0,%1,%2,%3}, [%4];"
                 : "=r"(r[0]), "=r"(r[1]), "=r"(r[2]), "=r"(r[3]) : "r"(a));
}
__device__ __forceinline__ void mma16816(float* d, const uint32_t* a, const uint32_t* b) {
    asm volatile(
        "mma.sync.aligned.m16n8k16.row.col.f32.f16.f16.f32 "
        "{%0,%1,%2,%3}, {%4,%5,%6,%7}, {%8,%9}, {%0,%1,%2,%3};"
        : "+f"(d[0]), "+f"(d[1]), "+f"(d[2]), "+f"(d[3])
        : "r"(a[0]), "r"(a[1]), "r"(a[2]), "r"(a[3]), "r"(b[0]), "r"(b[1]));
}

__device__ __forceinline__ uint32_t pack2(float a, float b) {
    __half2 t = __floats2half2_rn(a, b);
    return *(uint32_t*)&t;
}

// ================= fp16 mma.sync GEMM core (BK=64) =================
// C[M,N] = A[M,K] . B^T, B stored [N,K] row-major (pre-transposed).
// CTA tile 128x128, BK=64, 8 warps (4m x 2n), warp tile 32x64. 2 CTAs/SM.
#define GP    144     // smem pitch bytes per 64-fp16 row (conflict-free LDSM)
#define GMAT  (128 * GP)      // 18432
#define GSTG  (2 * GMAT)      // A + B per stage = 36864
#define GSMEM (2 * GSTG)      // 73728

template<int MODE>   // 0: fp32 out, 1: fp16 out (scaled)
__device__ __forceinline__ void gemm_core(
    uint32_t sb,
    const fp16* __restrict__ A, const fp16* __restrict__ B,
    float* __restrict__ Cf, fp16* __restrict__ Ch,
    int N, int K, int m0, int n0, float scale) {
    const int tid = threadIdx.x, lane = tid & 31, wid = tid >> 5;
    const int wm = (wid >> 1) << 5, wn = (wid & 1) << 6;

    const int arow  = (lane & 7) + ((lane >> 3) & 1) * 8;
    const int akoff = ((lane >> 4) << 3);
    const int brow  = (lane & 7) + ((lane >> 4) << 3);
    const int bkoff = ((lane >> 3) & 1) * 8;

    float acc[2][8][4];
    #pragma unroll
    for (int i = 0; i < 2; i++)
        #pragma unroll
        for (int j = 0; j < 8; j++)
            #pragma unroll
            for (int r = 0; r < 4; r++) acc[i][j][r] = 0.f;

    const int NCH = K >> 6;    // BK = 64

    {   // preload chunk 0: each matrix 128 rows x 128B = 1024 cp16, 4/thread
        #pragma unroll
        for (int i = 0; i < 4; i++) {
            int idx = tid + (i << 8);
            int row = idx >> 3, c = idx & 7;
            uint32_t off = row * GP + c * 16;
            cp16(sb + off,        A + (size_t)(m0 + row) * K + c * 8);
            cp16(sb + GMAT + off, B + (size_t)(n0 + row) * K + c * 8);
        }
    }
    CP_COMMIT();

    for (int ch = 0; ch < NCH; ch++) {
        if (ch + 1 < NCH) {
            uint32_t d = sb + ((ch + 1) & 1) * GSTG;
            int k0 = (ch + 1) << 6;
            #pragma unroll
            for (int i = 0; i < 4; i++) {
                int idx = tid + (i << 8);
                int row = idx >> 3, c = idx & 7;
                uint32_t off = row * GP + c * 16;
                cp16(d + off,        A + (size_t)(m0 + row) * K + k0 + c * 8);
                cp16(d + GMAT + off, B + (size_t)(n0 + row) * K + k0 + c * 8);
            }
        }
        CP_COMMIT();
        CP_WAIT1();
        __syncthreads();

        const uint32_t base = sb + (ch & 1) * GSTG;
        #pragma unroll
        for (int kk = 0; kk < 4; kk++) {
            uint32_t af[2][4];
            #pragma unroll
            for (int sm = 0; sm < 2; sm++) {
                uint32_t aoff = (wm + sm * 16 + arow) * GP + (kk * 16 + akoff) * 2;
                ldsm4(af[sm], base + aoff);
            }
            uint32_t bf4[4][4];
            #pragma unroll
            for (int q = 0; q < 4; q++) {
                uint32_t boff = (wn + q * 16 + brow) * GP + (kk * 16 + bkoff) * 2;
                ldsm4(bf4[q], base + GMAT + boff);
            }
            #pragma unroll
            for (int sm = 0; sm < 2; sm++)
                #pragma unroll
                for (int nt = 0; nt < 8; nt++)
                    mma16816(acc[sm][nt], af[sm], &bf4[nt >> 1][(nt & 1) << 1]);
        }
        __syncthreads();
    }

    const int r0 = wm + (lane >> 2);
    const int c0 = wn + ((lane & 3) << 1);
    #pragma unroll
    for (int sm = 0; sm < 2; sm++)
        #pragma unroll
        for (int nt = 0; nt < 8; nt++) {
            int row = m0 + r0 + sm * 16;
            int col = n0 + c0 + nt * 8;
            if (MODE == 0) {
                *(float2*)(Cf + (size_t)row * N + col) =
                    make_float2(acc[sm][nt][0], acc[sm][nt][1]);
                *(float2*)(Cf + (size_t)(row + 8) * N + col) =
                    make_float2(acc[sm][nt][2], acc[sm][nt][3]);
            } else {
                *(uint32_t*)(Ch + (size_t)row * N + col) =
                    pack2(acc[sm][nt][0] * scale, acc[sm][nt][1] * scale);
                *(uint32_t*)(Ch + (size_t)(row + 8) * N + col) =
                    pack2(acc[sm][nt][2] * scale, acc[sm][nt][3] * scale);
            }
        }
}

// merged q-proj + kv-proj (one launch, no wave tails)
__global__ __launch_bounds__(256, 2)
void proj_gemm(const fp16* __restrict__ qin, const fp16* __restrict__ kvin,
               const fp16* __restrict__ wq, const fp16* __restrict__ wkv,
               fp16* __restrict__ q, fp16* __restrict__ kv) {
    extern __shared__ __align__(128) char smem[];
    const uint32_t sb = smem_u32(smem);
    const int bx = blockIdx.x, m0 = blockIdx.y << 7;
    if (bx < HID / 128) {
        gemm_core<1>(sb, qin, wq, nullptr, q, HID, HID, m0, bx << 7, QSCALE);
    } else {
        gemm_core<1>(sb, kvin, wkv, nullptr, kv, 2 * HID, HID, m0, (bx - HID / 128) << 7, 1.0f);
    }
}

__global__ __launch_bounds__(256, 2)
void out_gemm(const fp16* __restrict__ y, const fp16* __restrict__ wc,
              float* __restrict__ out) {
    extern __shared__ __align__(128) char smem[];
    const uint32_t sb = smem_u32(smem);
    gemm_core<0>(sb, y, wc, out, nullptr, HID, HID, blockIdx.y << 7, blockIdx.x << 7, 0.f);
}

// ================= flash attention on fp16 mma.sync =================
// CTA: 64 queries x one (b,h), 128 threads / 4 warps. 128-row KV iters. 2 CTAs/SM.
#define AP     144                 // pitch bytes per 64-fp16 row
#define AQMAT  (64 * AP)           // 9216  (Q tile: 64 rows)
#define AM2    (128 * AP)          // one K or V matrix (128 rows) = 18432
#define ASTG   (2 * AM2)           // K+V per stage = 36864
#define ASMEM  (AQMAT + 2 * ASTG)  // 82944

__global__ __launch_bounds__(128, 2)
void attn_mma(const fp16* __restrict__ q, const fp16* __restrict__ kv,
              fp16* __restrict__ y) {
    extern __shared__ __align__(128) char smem[];
    const uint32_t sb = smem_u32(smem);
    const int tid = threadIdx.x, lane = tid & 31, wid = tid >> 5;
    const int bh = blockIdx.y;
    const int b = bh >> 4, h = bh & 15;
    const int q0 = blockIdx.x << 6;      // 64-query tiles

    const int arow  = (lane & 7) + ((lane >> 3) & 1) * 8;
    const int akoff = ((lane >> 4) << 3);
    const int brow  = (lane & 7) + ((lane >> 4) << 3);
    const int bkoff = ((lane >> 3) & 1) * 8;

    const uint32_t sQ  = sb;
    const uint32_t sKV = sb + AQMAT;

    // --- load Q tile (64 x 64) ---
    #pragma unroll
    for (int i = 0; i < 4; i++) {
        int idx = tid + (i << 7);
        int row = idx >> 3, c = idx & 7;
        cp16(sQ + row * AP + c * 16,
             q + (size_t)(b * SEQ + q0 + row) * HID + h * HEADDIM + c * 8);
    }
    CP_COMMIT();

    // --- preload KV iter 0 (128 rows of K and V) ---
    const size_t kvrow0 = (size_t)(b * SEQ);
    #pragma unroll
    for (int i = 0; i < 8; i++) {
        int idx = tid + (i << 7);
        int row = idx >> 3, c = idx & 7;
        uint32_t off = row * AP + c * 16;
        size_t gk = (kvrow0 + row) * (2 * HID) + h * HEADDIM + c * 8;
        cp16(sKV + off,       kv + gk);
        cp16(sKV + AM2 + off, kv + gk + HID);
    }
    CP_COMMIT();
    CP_WAIT1();        // Q resident
    __syncthreads();

    uint32_t qf[4][4];
    #pragma unroll
    for (int kk = 0; kk < 4; kk++)
        ldsm4(qf[kk], sQ + (wid * 16 + arow) * AP + (kk * 16 + akoff) * 2);

    float o[8][4];
    #pragma unroll
    for (int i = 0; i < 8; i++)
        #pragma unroll
        for (int r = 0; r < 4; r++) o[i][r] = 0.f;
    float m0_ = -INFINITY, m1_ = -INFINITY, l0_ = 0.f, l1_ = 0.f;

    const int NIT = SEQ / 128;
    for (int ch = 0; ch < NIT; ch++) {
        if (ch + 1 < NIT) {
            uint32_t d = sKV + ((ch + 1) & 1) * ASTG;
            int t0 = (ch + 1) << 7;
            #pragma unroll
            for (int i = 0; i < 8; i++) {
                int idx = tid + (i << 7);
                int row = idx >> 3, c = idx & 7;
                uint32_t off = row * AP + c * 16;
                size_t gk = (kvrow0 + t0 + row) * (2 * HID) + h * HEADDIM + c * 8;
                cp16(d + off,       kv + gk);
                cp16(d + AM2 + off, kv + gk + HID);
            }
        }
        CP_COMMIT();
        CP_WAIT1();
        __syncthreads();

        const uint32_t sK = sKV + (ch & 1) * ASTG;
        const uint32_t sV = sK + AM2;

        // ---- S_A (keys 0-63), S_B (keys 64-127) ----
        float sA[8][4], sB[8][4];
        #pragma unroll
        for (int i = 0; i < 8; i++)
            #pragma unroll
            for (int r = 0; r < 4; r++) { sA[i][r] = 0.f; sB[i][r] = 0.f; }

        #pragma unroll
        for (int kk = 0; kk < 4; kk++) {
            uint32_t kb[4][4];
            #pragma unroll
            for (int g = 0; g < 4; g++)
                ldsm4(kb[g], sK + (g * 16 + brow) * AP + (kk * 16 + bkoff) * 2);
            #pragma unroll
            for (int nt = 0; nt < 8; nt++)
                mma16816(sA[nt], qf[kk], &kb[nt >> 1][(nt & 1) << 1]);
        }
        #pragma unroll
        for (int kk = 0; kk < 4; kk++) {
            uint32_t kb[4][4];
            #pragma unroll
            for (int g = 0; g < 4; g++)
                ldsm4(kb[g], sK + ((64 + g * 16) + brow) * AP + (kk * 16 + bkoff) * 2);
            #pragma unroll
            for (int nt = 0; nt < 8; nt++)
                mma16816(sB[nt], qf[kk], &kb[nt >> 1][(nt & 1) << 1]);
        }

        // ---- single online-softmax update over 128 keys ----
        float mx0 = -INFINITY, mx1 = -INFINITY;
        #pragma unroll
        for (int nt = 0; nt < 8; nt++) {
            mx0 = fmaxf(mx0, fmaxf(fmaxf(sA[nt][0], sA[nt][1]), fmaxf(sB[nt][0], sB[nt][1])));
            mx1 = fmaxf(mx1, fmaxf(fmaxf(sA[nt][2], sA[nt][3]), fmaxf(sB[nt][2], sB[nt][3])));
        }
        mx0 = fmaxf(mx0, __shfl_xor_sync(0xffffffffu, mx0, 1));
        mx0 = fmaxf(mx0, __shfl_xor_sync(0xffffffffu, mx0, 2));
        mx1 = fmaxf(mx1, __shfl_xor_sync(0xffffffffu, mx1, 1));
        mx1 = fmaxf(mx1, __shfl_xor_sync(0xffffffffu, mx1, 2));
        float mn0 = fmaxf(m0_, mx0), mn1 = fmaxf(m1_, mx1);
        float corr0 = exp2f(m0_ - mn0), corr1 = exp2f(m1_ - mn1);
        m0_ = mn0; m1_ = mn1;

        float rs0 = 0.f, rs1 = 0.f;
        uint32_t phA[4][4];
        #pragma unroll
        for (int nt = 0; nt < 8; nt++) {
            sA[nt][0] = exp2f(sA[nt][0] - mn0); rs0 += sA[nt][0];
            sA[nt][1] = exp2f(sA[nt][1] - mn0); rs0 += sA[nt][1];
            sA[nt][2] = exp2f(sA[nt][2] - mn1); rs1 += sA[nt][2];
            sA[nt][3] = exp2f(sA[nt][3] - mn1); rs1 += sA[nt][3];
        }
        #pragma unroll
        for (int j = 0; j < 4; j++) {
            phA[j][0] = pack2(sA[2*j][0], sA[2*j][1]);
            phA[j][1] = pack2(sA[2*j][2], sA[2*j][3]);
            phA[j][2] = pack2(sA[2*j+1][0], sA[2*j+1][1]);
            phA[j][3] = pack2(sA[2*j+1][2], sA[2*j+1][3]);
        }

        #pragma unroll
        for (int dt = 0; dt < 8; dt++) {
            o[dt][0] *= corr0; o[dt][1] *= corr0;
            o[dt][2] *= corr1; o[dt][3] *= corr1;
        }

        // ---- PV(A); softmax(B) ALU interleaves with these MMAs ----
        #pragma unroll
        for (int j = 0; j < 4; j++) {
            uint32_t vb[4][4];
            #pragma unroll
            for (int dq = 0; dq < 4; dq++)
                ldsm4t(vb[dq], sV + (j * 16 + arow) * AP + (dq * 16 + akoff) * 2);
            #pragma unroll
            for (int dt = 0; dt < 8; dt++)
                mma16816(o[dt], phA[j], &vb[dt >> 1][(dt & 1) << 1]);
        }

        uint32_t phB[4][4];
        #pragma unroll
        for (int nt = 0; nt < 8; nt++) {
            sB[nt][0] = exp2f(sB[nt][0] - mn0); rs0 += sB[nt][0];
            sB[nt][1] = exp2f(sB[nt][1] - mn0); rs0 += sB[nt][1];
            sB[nt][2] = exp2f(sB[nt][2] - mn1); rs1 += sB[nt][2];
            sB[nt][3] = exp2f(sB[nt][3] - mn1); rs1 += sB[nt][3];
        }
        #pragma unroll
        for (int j = 0; j < 4; j++) {
            phB[j][0] = pack2(sB[2*j][0], sB[2*j][1]);
            phB[j][1] = pack2(sB[2*j][2], sB[2*j][3]);
            phB[j][2] = pack2(sB[2*j+1][0], sB[2*j+1][1]);
            phB[j][3] = pack2(sB[2*j+1][2], sB[2*j+1][3]);
        }

        rs0 += __shfl_xor_sync(0xffffffffu, rs0, 1);
        rs0 += __shfl_xor_sync(0xffffffffu, rs0, 2);
        rs1 += __shfl_xor_sync(0xffffffffu, rs1, 1);
        rs1 += __shfl_xor_sync(0xffffffffu, rs1, 2);
        l0_ = l0_ * corr0 + rs0;
        l1_ = l1_ * corr1 + rs1;

        // ---- PV(B) ----
        #pragma unroll
        for (int j = 0; j < 4; j++) {
            uint32_t vb[4][4];
            #pragma unroll
            for (int dq = 0; dq < 4; dq++)
                ldsm4t(vb[dq], sV + ((64 + j * 16) + arow) * AP + (dq * 16 + akoff) * 2);
            #pragma unroll
            for (int dt = 0; dt < 8; dt++)
                mma16816(o[dt], phB[j], &vb[dt >> 1][(dt & 1) << 1]);
        }
        __syncthreads();
    }

    // ---- epilogue: normalize, store y (fp16) ----
    const float inv0 = 1.f / l0_, inv1 = 1.f / l1_;
    const int gr = b * SEQ + q0 + wid * 16 + (lane >> 2);
    const int col = h * HEADDIM + ((lane & 3) << 1);
    #pragma unroll
    for (int dt = 0; dt < 8; dt++) {
        *(uint32_t*)(y + (size_t)gr * HID + col + dt * 8) =
            pack2(o[dt][0] * inv0, o[dt][1] * inv0);
        *(uint32_t*)(y + (size_t)(gr + 8) * HID + col + dt * 8) =
            pack2(o[dt][2] * inv1, o[dt][3] * inv1);
    }
}

// ================= fused prep: act converts + 3 coalesced weight transposes ====
#define ACT_BLKS (MROWS * HID / 4 / 256)     // 4096
#define WQ_TILES ((HID / 64) * (HID / 64))       // 256
#define WKV_TILES ((2 * HID / 64) * (HID / 64))  // 512
#define WC_TILES WQ_TILES                        // 256

__device__ __forceinline__ void act_conv_blk(const float* __restrict__ in,
                                             fp16* __restrict__ h, int blk, int tid) {
    int i = ((blk * 256 + tid) << 2);
    float4 v = *(const float4*)(in + i);
    *(uint32_t*)(h + i)     = pack2(v.x, v.y);
    *(uint32_t*)(h + i + 2) = pack2(v.z, v.w);
}

// 64x64 transpose tile: W[K,Nstride] fp32 (pre-offset) -> T[N,K] fp16.
// Output rows written 128B-contiguous (16 halves = 32B per thread).
__device__ __forceinline__ void trconv64(const float* __restrict__ W, fp16* __restrict__ T,
                                         int Nstride, int n0, int k0, int tid,
                                         float* s /* [64*65] */) {
    #pragma unroll
    for (int i = 0; i < 4; i++) {
        int idx = tid + (i << 8);
        int r = idx >> 4, c4 = (idx & 15) << 2;
        float4 v = *(const float4*)(W + (size_t)(k0 + r) * Nstride + n0 + c4);
        s[r * 65 + c4 + 0] = v.x;
        s[r * 65 + c4 + 1] = v.y;
        s[r * 65 + c4 + 2] = v.z;
        s[r * 65 + c4 + 3] = v.w;
    }
    __syncthreads();
    const int n = tid >> 2, kk = (tid & 3) << 4;
    uint32_t o[8];
    #pragma unroll
    for (int i = 0; i < 8; i++)
        o[i] = pack2(s[(kk + 2 * i) * 65 + n], s[(kk + 2 * i + 1) * 65 + n]);
    fp16* dst = T + (size_t)(n0 + n) * HID + k0 + kk;
    *(uint4*)dst       = make_uint4(o[0], o[1], o[2], o[3]);
    *(uint4*)(dst + 8) = make_uint4(o[4], o[5], o[6], o[7]);
    __syncthreads();
}

__global__ void prep(const float* __restrict__ query, const float* __restrict__ key_value,
                     const float* __restrict__ Wq, const float* __restrict__ Wkv,
                     const float* __restrict__ Wc,
                     fp16* __restrict__ qin, fp16* __restrict__ kvin,
                     fp16* __restrict__ wqT, fp16* __restrict__ wkvT,
                     fp16* __restrict__ wcT) {
    __shared__ float s[64 * 65];
    const int tid = threadIdx.x;
    int b = blockIdx.x;
    if (b < ACT_BLKS) { act_conv_blk(query, qin, b, tid); return; }
    b -= ACT_BLKS;
    if (b < ACT_BLKS) { act_conv_blk(key_value, kvin, b, tid); return; }
    b -= ACT_BLKS;
    if (b < WQ_TILES) {
        int nt = b & 15, kt = b >> 4;
        trconv64(Wq, wqT, HID, nt << 6, kt << 6, tid, s);
        return;
    }
    b -= WQ_TILES;
    if (b < WKV_TILES) {
        int nt = b & 31, kt = b >> 5;
        trconv64(Wkv, wkvT, 2 * HID, nt << 6, kt << 6, tid, s);
        return;
    }
    b -= WKV_TILES;
    {
        int nt = b & 15, kt = b >> 4;
        trconv64(Wc, wcT, HID, nt << 6, kt << 6, tid, s);
    }
}

// ---------------- launch ----------------
extern "C" void kernel_launch(void* const* d_in, const int* in_sizes, int n_in,
                              void* d_out, int out_size) {
    const float* query     = (const float*)d_in[0];
    const float* key_value = (const float*)d_in[1];
    const float* Wq        = (const float*)d_in[2];
    const float* Wkv       = (const float*)d_in[3];
    const float* Wc        = (const float*)d_in[4];
    float* out = (float*)d_out;

    fp16 *qin, *kvin, *q, *kv, *y, *wqT, *wkvT, *wcT;
    cudaGetSymbolAddress((void**)&qin,  g_qin);
    cudaGetSymbolAddress((void**)&kvin, g_kvin);
    cudaGetSymbolAddress((void**)&q,    g_q);
    cudaGetSymbolAddress((void**)&kv,   g_kv);
    cudaGetSymbolAddress((void**)&y,    g_y);
    cudaGetSymbolAddress((void**)&wqT,  g_wqT);
    cudaGetSymbolAddress((void**)&wkvT, g_wkvT);
    cudaGetSymbolAddress((void**)&wcT,  g_wcT);

    cudaFuncSetAttribute(proj_gemm, cudaFuncAttributeMaxDynamicSharedMemorySize, GSMEM);
    cudaFuncSetAttribute(out_gemm,  cudaFuncAttributeMaxDynamicSharedMemorySize, GSMEM);
    cudaFuncSetAttribute(attn_mma,  cudaFuncAttributeMaxDynamicSharedMemorySize, ASMEM);

    // one fused prep launch: both act converts + all 3 weight transposes
    prep<<<2 * ACT_BLKS + WQ_TILES + WKV_TILES + WC_TILES, 256>>>(
        query, key_value, Wq, Wkv, Wc, qin, kvin, wqT, wkvT, wcT);

    // merged projections: bx<8 -> q-proj (QSCALE folded), else kv-proj
    proj_gemm<<<dim3(HID / 128 + 2 * HID / 128, MROWS / 128), 256, GSMEM>>>(
        qin, kvin, wqT, wkvT, q, kv);

    // attention: 64-query CTAs, 128 threads, 2 CTAs/SM
    attn_mma<<<dim3(SEQ / 64, BATCH * NHEADS), 128, ASMEM>>>(q, kv, y);

    out_gemm<<<dim3(HID / 128, MROWS / 128), 256, GSMEM>>>(y, wcT, out);
}